// round 12
// baseline (speedup 1.0000x reference)
#include <cuda_runtime.h>
#include <cuda_bf16.h>
#include <math.h>

#define B 16
typedef unsigned long long ull;

// ---------------------------------------------------------------------------
// f32x2 packed helpers (Blackwell dual-fp32 pipe)
// ---------------------------------------------------------------------------
__device__ __forceinline__ void ffma2(ull &acc, ull a, ull b) {
    asm("fma.rn.f32x2 %0, %1, %2, %0;" : "+l"(acc) : "l"(a), "l"(b));
}
__device__ __forceinline__ ull pack2(float a, float b) {
    ull r; asm("mov.b64 %0, {%1, %2};" : "=l"(r) : "f"(a), "f"(b)); return r;
}
__device__ __forceinline__ float2 unpack2(ull v) {
    float2 r; asm("mov.b64 {%0, %1}, %2;" : "=f"(r.x), "=f"(r.y) : "l"(v)); return r;
}

// ---------------------------------------------------------------------------
// Scratch (device globals; no allocation allowed)
// ---------------------------------------------------------------------------
__device__ float g_h1[B*64*128*128];
__device__ float g_h2[B*128*64*64];
__device__ float g_tok[B*1024*256];
__device__ float g_q[B*256*32*32];
__device__ float g_d1[B*128*64*64];
__device__ float g_d2[B*64*128*128];
__device__ int   g_idx[B*1024];
__device__ float g_pv[2*B*1024];
__device__ int   g_pi[2*B*1024];

// ---------------------------------------------------------------------------
// Direct conv k=4 s=2 p=1, 16 oc per block, 2 pixels/thread (verified).
// tok_mode=1: write y[token][channel] (fused transpose for conv3).
// ---------------------------------------------------------------------------
__global__ __launch_bounds__(256, 2)
void conv_k4s2_oc16(const float* __restrict__ x, const float* __restrict__ w,
                    const float* __restrict__ bias, float* __restrict__ y,
                    int N, int Cin, int Cout, int Hin, int Win, int relu,
                    int tok_mode)
{
    const int Hout = Hin >> 1, Wout = Win >> 1;
    const int ng = (Cout + 15) >> 4;
    const int n  = blockIdx.z / ng;
    const int oc0 = (blockIdx.z % ng) << 4;
    const int ox0 = blockIdx.x * 32 + threadIdx.x;
    const int oy  = blockIdx.y * 16 + threadIdx.y;
    const int tid = threadIdx.y * 16 + threadIdx.x;

    __shared__ float wsm[32][16][16];

    int iy[4]; bool oky[4];
    int ixA[4], ixB[4]; bool okA[4], okB[4];
#pragma unroll
    for (int k = 0; k < 4; k++) {
        int t = oy * 2 + k - 1;
        iy[k] = t; oky[k] = (unsigned)t < (unsigned)Hin;
        int sA = ox0 * 2 + k - 1;
        ixA[k] = sA; okA[k] = (unsigned)sA < (unsigned)Win;
        int sB = sA + 32;
        ixB[k] = sB; okB[k] = (unsigned)sB < (unsigned)Win;
    }

    ull acc[2][8];
#pragma unroll
    for (int p = 0; p < 2; p++)
#pragma unroll
        for (int j = 0; j < 8; j++) acc[p][j] = 0ull;

    for (int ic0 = 0; ic0 < Cin; ic0 += 32) {
        const int icc = min(32, Cin - ic0);
        __syncthreads();
        for (int i = tid; i < icc * 256; i += 256) {
            int c = i >> 8, rem = i & 255, t = rem >> 4, o = rem & 15;
            float wv = 0.f;
            if (oc0 + o < Cout)
                wv = w[(((oc0 + o) * Cin + ic0 + c) << 4) + t];
            wsm[c][t][o] = wv;
        }
        __syncthreads();

        const float* xp = x + ((size_t)(n * Cin + ic0) * Hin) * Win;
        for (int c = 0; c < icc; c++) {
            const float* xc = xp + (size_t)c * Hin * Win;
#pragma unroll
            for (int ky = 0; ky < 4; ky++) {
                if (!oky[ky]) continue;
                const float* xr = xc + iy[ky] * Win;
#pragma unroll
                for (int kx = 0; kx < 4; kx++) {
                    float v0 = okA[kx] ? __ldg(&xr[ixA[kx]]) : 0.f;
                    float v1 = okB[kx] ? __ldg(&xr[ixB[kx]]) : 0.f;
                    ull v0d = pack2(v0, v0);
                    ull v1d = pack2(v1, v1);
                    const ulonglong2* wq = (const ulonglong2*)&wsm[c][ky * 4 + kx][0];
                    ulonglong2 wv0 = wq[0];
                    ulonglong2 wv1 = wq[1];
                    ulonglong2 wv2 = wq[2];
                    ulonglong2 wv3 = wq[3];
                    ffma2(acc[0][0], v0d, wv0.x); ffma2(acc[1][0], v1d, wv0.x);
                    ffma2(acc[0][1], v0d, wv0.y); ffma2(acc[1][1], v1d, wv0.y);
                    ffma2(acc[0][2], v0d, wv1.x); ffma2(acc[1][2], v1d, wv1.x);
                    ffma2(acc[0][3], v0d, wv1.y); ffma2(acc[1][3], v1d, wv1.y);
                    ffma2(acc[0][4], v0d, wv2.x); ffma2(acc[1][4], v1d, wv2.x);
                    ffma2(acc[0][5], v0d, wv2.y); ffma2(acc[1][5], v1d, wv2.y);
                    ffma2(acc[0][6], v0d, wv3.x); ffma2(acc[1][6], v1d, wv3.x);
                    ffma2(acc[0][7], v0d, wv3.y); ffma2(acc[1][7], v1d, wv3.y);
                }
            }
        }
    }

#pragma unroll
    for (int p = 0; p < 2; p++) {
        int ox = ox0 + 16 * p;
        if (ox >= Wout) continue;
        if (tok_mode) {
            float* dst = y + ((size_t)((n * Hout + oy) * Wout + ox)) * Cout + oc0;
#pragma unroll
            for (int j = 0; j < 8; j++) {
                float2 r = unpack2(acc[p][j]);
                r.x += bias[oc0 + 2 * j];
                r.y += bias[oc0 + 2 * j + 1];
                if (relu) { r.x = fmaxf(r.x, 0.f); r.y = fmaxf(r.y, 0.f); }
                *(float2*)&dst[2 * j] = r;
            }
        } else {
#pragma unroll
            for (int j = 0; j < 8; j++) {
                float2 r = unpack2(acc[p][j]);
                int oc = oc0 + 2 * j;
                if (oc < Cout) {
                    float v = r.x + bias[oc];
                    if (relu) v = fmaxf(v, 0.f);
                    y[(((size_t)n * Cout + oc) * Hout + oy) * Wout + ox] = v;
                }
                if (oc + 1 < Cout) {
                    float v = r.y + bias[oc + 1];
                    if (relu) v = fmaxf(v, 0.f);
                    y[(((size_t)n * Cout + oc + 1) * Hout + oy) * Wout + ox] = v;
                }
            }
        }
    }
}

// ---------------------------------------------------------------------------
// Transposed conv k=4 s=2 p=1, 16 oc per block (verified).
// ---------------------------------------------------------------------------
__global__ __launch_bounds__(256, 2)
void deconv_k4s2_oc16(const float* __restrict__ x, const float* __restrict__ w,
                      const float* __restrict__ bias, float* __restrict__ y,
                      int N, int Cin, int Cout, int Hin, int Win, int relu)
{
    const int Hout = Hin << 1, Wout = Win << 1;
    const int ng = (Cout + 15) >> 4;
    const int n  = blockIdx.z / ng;
    const int oc0 = (blockIdx.z % ng) << 4;
    const int ox0 = blockIdx.x * 32 + threadIdx.x;
    const int oy  = blockIdx.y * 16 + threadIdx.y;
    const int tid = threadIdx.y * 16 + threadIdx.x;

    const int pr = oy & 1, q = ox0 & 1;
    int rofs[2], tapy[2]; bool vy[2];
    int ixA[2], ixB[2], tapx[2]; bool vA[2], vB[2];
#pragma unroll
    for (int a = 0; a < 2; a++) {
        int ky = pr + 2 * a; int t = oy + ky - 2;
        rofs[a] = (t >> 1) * Win;
        vy[a] = (t >= 0) && ((t >> 1) < Hin);
        tapy[a] = ky;
        int kx = q + 2 * a;
        int sA = ox0 + kx - 2;
        ixA[a] = sA >> 1; vA[a] = (sA >= 0) && ((sA >> 1) < Win);
        int sB = sA + 16;
        ixB[a] = sB >> 1; vB[a] = (sB >= 0) && ((sB >> 1) < Win);
        tapx[a] = kx;
    }

    __shared__ float wsm[32][16][16];

    ull acc[2][8];
#pragma unroll
    for (int pp = 0; pp < 2; pp++)
#pragma unroll
        for (int j = 0; j < 8; j++) acc[pp][j] = 0ull;

    for (int ic0 = 0; ic0 < Cin; ic0 += 32) {
        const int icc = min(32, Cin - ic0);
        __syncthreads();
        for (int i = tid; i < icc * 256; i += 256) {
            int c = i >> 8, rem = i & 255, t = rem >> 4, o = rem & 15;
            float wv = 0.f;
            if (oc0 + o < Cout)
                wv = w[(((oc0 + o) * Cin + ic0 + c) << 4) + t];
            wsm[c][t][o] = wv;
        }
        __syncthreads();

        const float* xp = x + ((size_t)(n * Cin + ic0) * Hin) * Win;
        for (int c = 0; c < icc; c++) {
            const float* xc = xp + (size_t)c * Hin * Win;
#pragma unroll
            for (int a = 0; a < 2; a++) {
                if (!vy[a]) continue;
                const float* xr = xc + rofs[a];
#pragma unroll
                for (int b2 = 0; b2 < 2; b2++) {
                    float v0 = vA[b2] ? __ldg(&xr[ixA[b2]]) : 0.f;
                    float v1 = vB[b2] ? __ldg(&xr[ixB[b2]]) : 0.f;
                    ull v0d = pack2(v0, v0);
                    ull v1d = pack2(v1, v1);
                    const ulonglong2* wq = (const ulonglong2*)&wsm[c][tapy[a] * 4 + tapx[b2]][0];
                    ulonglong2 wv0 = wq[0];
                    ulonglong2 wv1 = wq[1];
                    ulonglong2 wv2 = wq[2];
                    ulonglong2 wv3 = wq[3];
                    ffma2(acc[0][0], v0d, wv0.x); ffma2(acc[1][0], v1d, wv0.x);
                    ffma2(acc[0][1], v0d, wv0.y); ffma2(acc[1][1], v1d, wv0.y);
                    ffma2(acc[0][2], v0d, wv1.x); ffma2(acc[1][2], v1d, wv1.x);
                    ffma2(acc[0][3], v0d, wv1.y); ffma2(acc[1][3], v1d, wv1.y);
                    ffma2(acc[0][4], v0d, wv2.x); ffma2(acc[1][4], v1d, wv2.x);
                    ffma2(acc[0][5], v0d, wv2.y); ffma2(acc[1][5], v1d, wv2.y);
                    ffma2(acc[0][6], v0d, wv3.x); ffma2(acc[1][6], v1d, wv3.x);
                    ffma2(acc[0][7], v0d, wv3.y); ffma2(acc[1][7], v1d, wv3.y);
                }
            }
        }
    }

#pragma unroll
    for (int pp = 0; pp < 2; pp++) {
        int ox = ox0 + 16 * pp;
        if (ox >= Wout) continue;
#pragma unroll
        for (int j = 0; j < 8; j++) {
            float2 r = unpack2(acc[pp][j]);
            int oc = oc0 + 2 * j;
            if (oc < Cout) {
                float v = r.x + bias[oc];
                if (relu) v = fmaxf(v, 0.f);
                y[(((size_t)n * Cout + oc) * Hout + oy) * Wout + ox] = v;
            }
            if (oc + 1 < Cout) {
                float v = r.y + bias[oc + 1];
                if (relu) v = fmaxf(v, 0.f);
                y[(((size_t)n * Cout + oc + 1) * Hout + oy) * Wout + ox] = v;
            }
        }
    }
}

// ---------------------------------------------------------------------------
// 8-oc deconv (deconv3, Cout=3), LDS.128 weights (verified).
// ---------------------------------------------------------------------------
__global__ __launch_bounds__(256)
void deconv_k4s2(const float* __restrict__ x, const float* __restrict__ w,
                 const float* __restrict__ bias, float* __restrict__ y,
                 int N, int Cin, int Cout, int Hin, int Win, int relu)
{
    const int Hout = Hin << 1, Wout = Win << 1;
    const int ng = (Cout + 7) >> 3;
    const int n  = blockIdx.z / ng;
    const int oc0 = (blockIdx.z % ng) << 3;
    const int ox0 = blockIdx.x * 32 + threadIdx.x;
    const int oy  = blockIdx.y * 16 + threadIdx.y;
    const int tid = threadIdx.y * 16 + threadIdx.x;

    const int p = oy & 1, q = ox0 & 1;
    int iyv[2], tapy[2]; bool vy[2];
    int ixA[2], ixB[2], tapx[2]; bool vA[2], vB[2];
#pragma unroll
    for (int a = 0; a < 2; a++) {
        int ky = p + 2 * a; int t = oy + ky - 2;
        iyv[a] = t >> 1; vy[a] = (t >= 0) && ((t >> 1) < Hin); tapy[a] = ky;
        int kx = q + 2 * a;
        int sA = ox0 + kx - 2;
        ixA[a] = sA >> 1; vA[a] = (sA >= 0) && ((sA >> 1) < Win);
        int sB = sA + 16;
        ixB[a] = sB >> 1; vB[a] = (sB >= 0) && ((sB >> 1) < Win);
        tapx[a] = kx;
    }

    __shared__ float wsm[64][16][8];

    ull acc[2][4];
#pragma unroll
    for (int pp = 0; pp < 2; pp++)
#pragma unroll
        for (int j = 0; j < 4; j++) acc[pp][j] = 0ull;

    for (int ic0 = 0; ic0 < Cin; ic0 += 64) {
        const int icc = min(64, Cin - ic0);
        __syncthreads();
        for (int i = tid; i < icc * 128; i += 256) {
            int c = i >> 7, rem = i & 127, t = rem >> 3, o = rem & 7;
            float wv = 0.f;
            if (oc0 + o < Cout)
                wv = w[(((oc0 + o) * Cin + ic0 + c) << 4) + t];
            wsm[c][t][o] = wv;
        }
        __syncthreads();

        const float* xp = x + ((size_t)(n * Cin + ic0) * Hin) * Win;
        for (int c = 0; c < icc; c++) {
            const float* xc = xp + (size_t)c * Hin * Win;
#pragma unroll
            for (int a = 0; a < 2; a++) {
                if (!vy[a]) continue;
                const float* xr = xc + iyv[a] * Win;
#pragma unroll
                for (int b2 = 0; b2 < 2; b2++) {
                    float v0 = vA[b2] ? __ldg(&xr[ixA[b2]]) : 0.f;
                    float v1 = vB[b2] ? __ldg(&xr[ixB[b2]]) : 0.f;
                    ull v0d = pack2(v0, v0);
                    ull v1d = pack2(v1, v1);
                    const ulonglong2* wq = (const ulonglong2*)&wsm[c][tapy[a] * 4 + tapx[b2]][0];
                    ulonglong2 wv0 = wq[0];
                    ulonglong2 wv1 = wq[1];
                    ffma2(acc[0][0], v0d, wv0.x); ffma2(acc[1][0], v1d, wv0.x);
                    ffma2(acc[0][1], v0d, wv0.y); ffma2(acc[1][1], v1d, wv0.y);
                    ffma2(acc[0][2], v0d, wv1.x); ffma2(acc[1][2], v1d, wv1.x);
                    ffma2(acc[0][3], v0d, wv1.y); ffma2(acc[1][3], v1d, wv1.y);
                }
            }
        }
    }

#pragma unroll
    for (int pp = 0; pp < 2; pp++) {
        int ox = ox0 + 16 * pp;
        if (ox >= Wout) continue;
#pragma unroll
        for (int j = 0; j < 4; j++) {
            float2 r = unpack2(acc[pp][j]);
            int oc = oc0 + 2 * j;
            if (oc < Cout) {
                float v = r.x + bias[oc];
                if (relu) v = fmaxf(v, 0.f);
                y[(((size_t)n * Cout + oc) * Hout + oy) * Wout + ox] = v;
            }
            if (oc + 1 < Cout) {
                float v = r.y + bias[oc + 1];
                if (relu) v = fmaxf(v, 0.f);
                y[(((size_t)n * Cout + oc + 1) * Hout + oy) * Wout + ox] = v;
            }
        }
    }
}

// ---------------------------------------------------------------------------
// Argmax GEMM v5: dedup-free access pattern.
// Thread tile 2m x 8n: lane covers token rows {lane, lane+32} (32 unique
// a-addresses per LDS.128), warp w covers cb rows 8w..8w+7 (b-loads are
// single-address broadcasts).  Warp-private double-buffered Bsw.
// ---------------------------------------------------------------------------
#define AS_STRIDE 260
#define BSW_STRIDE 68
#define GEMM_SMEM_BYTES ((64*AS_STRIDE + 8*2*8*BSW_STRIDE + 64*8 + 64*8) * 4)

__global__ __launch_bounds__(256, 2)
void argmax_gemm(const float* __restrict__ tok, const float* __restrict__ cb,
                 float* __restrict__ pv, int* __restrict__ pi)
{
    extern __shared__ float dyn[];
    float (*As)[AS_STRIDE] = (float (*)[AS_STRIDE])dyn;
    float (*Bsw)[2][8][BSW_STRIDE] = (float (*)[2][8][BSW_STRIDE])(dyn + 64 * AS_STRIDE);
    float (*rv)[8] = (float (*)[8])(dyn + 64 * AS_STRIDE + 8 * 2 * 8 * BSW_STRIDE);
    int   (*ri)[8] = (int   (*)[8])(dyn + 64 * AS_STRIDE + 8 * 2 * 8 * BSW_STRIDE + 64 * 8);

    const int tid  = threadIdx.x;
    const int wid  = tid >> 5;            // warp 0..7
    const int lane = tid & 31;
    const int t0 = (blockIdx.x >> 1) * 64;
    const int half = blockIdx.x & 1;
    const int jhalf0 = half * 4096;

    // As fill mapping (block-wide)
    const int fr  = tid >> 2;
    const int fca = (tid & 3) << 6;

    // Bsw fill mapping (warp-local): lane -> local row lr 0..7, col seg
    const int lr   = lane >> 2;
    const int fcsb = (lane & 3) << 4;
    const int growofs = 8 * wid + lr;     // cb row within 64-row chunk

    // ---- fill As once ----
    {
        const float4* src = (const float4*)&tok[(size_t)(t0 + fr) * 256 + fca];
#pragma unroll
        for (int u = 0; u < 16; u++)
            *(float4*)&As[fr][fca + 4 * u] = src[u];
    }

    // ---- warp-private prefetch of stage 0 ----
    float4 pre[4];
    {
        const float4* src = (const float4*)&cb[(size_t)(jhalf0 + growofs) * 256 + fcsb];
#pragma unroll
        for (int u = 0; u < 4; u++) pre[u] = src[u];
#pragma unroll
        for (int u = 0; u < 4; u++)
            *(float4*)&Bsw[wid][0][lr][fcsb + 4 * u] = pre[u];
    }
    __syncthreads();

    float bv[2]; int bi[2];
#pragma unroll
    for (int m = 0; m < 2; m++) { bv[m] = -INFINITY; bi[m] = 0; }

    ull cacc[2][8];

    for (int s = 0; s < 256; s++) {
        const int buf = s & 1;
        const int k0 = (s & 3) << 6;

        if ((s & 3) == 0) {
#pragma unroll
            for (int m = 0; m < 2; m++)
#pragma unroll
                for (int nn = 0; nn < 8; nn++) cacc[m][nn] = 0ull;
        }

        if (s < 255) {   // register prefetch of next stage (warp-local)
            const int s1 = s + 1;
            const int jb = jhalf0 + (s1 >> 2) * 64;
            const int k1 = (s1 & 3) << 6;
            const float4* src = (const float4*)&cb[(size_t)(jb + growofs) * 256 + k1 + fcsb];
#pragma unroll
            for (int u = 0; u < 4; u++) pre[u] = src[u];
        }

#pragma unroll 4
        for (int kq = 0; kq < 16; kq++) {        // 16 steps x 4 k-values
            const int ka = k0 + 4 * kq;
            const int kb = 4 * kq;
            ulonglong2 a0 = *(const ulonglong2*)&As[lane][ka];
            ulonglong2 a1 = *(const ulonglong2*)&As[lane + 32][ka];
#pragma unroll
            for (int nn = 0; nn < 8; nn++) {
                ulonglong2 b = *(const ulonglong2*)&Bsw[wid][buf][nn][kb];
                ffma2(cacc[0][nn], a0.x, b.x);
                ffma2(cacc[0][nn], a0.y, b.y);
                ffma2(cacc[1][nn], a1.x, b.x);
                ffma2(cacc[1][nn], a1.y, b.y);
            }
        }

        if ((s & 3) == 3) {
            const int jbase = jhalf0 + (s >> 2) * 64 + 8 * wid;
#pragma unroll
            for (int m = 0; m < 2; m++)
#pragma unroll
                for (int nn = 0; nn < 8; nn++) {
                    float2 sv = unpack2(cacc[m][nn]);
                    float v = sv.x + sv.y;
                    int j = jbase + nn;
                    if (v > bv[m] || (v == bv[m] && j < bi[m])) { bv[m] = v; bi[m] = j; }
                }
        }

        if (s < 255) {
            __syncwarp();
#pragma unroll
            for (int u = 0; u < 4; u++)
                *(float4*)&Bsw[wid][(s + 1) & 1][lr][fcsb + 4 * u] = pre[u];
            __syncwarp();
        }
    }

    rv[lane][wid]      = bv[0]; ri[lane][wid]      = bi[0];
    rv[lane + 32][wid] = bv[1]; ri[lane + 32][wid] = bi[1];
    __syncthreads();
    if (tid < 64) {
        float best = rv[tid][0]; int bidx = ri[tid][0];
#pragma unroll
        for (int g = 1; g < 8; g++) {
            float v = rv[tid][g]; int j = ri[tid][g];
            if (v > best || (v == best && j < bidx)) { best = v; bidx = j; }
        }
        pv[half * (B * 1024) + t0 + tid] = best;
        pi[half * (B * 1024) + t0 + tid] = bidx;
    }
}

__global__ void merge_idx(const float* __restrict__ pv, const int* __restrict__ pi,
                          int* __restrict__ idx)
{
    int t = blockIdx.x * 256 + threadIdx.x;
    if (t >= B * 1024) return;
    float v0 = pv[t], v1 = pv[B * 1024 + t];
    idx[t] = (v1 > v0) ? pi[B * 1024 + t] : pi[t];   // half 0 wins ties (lower j)
}

__global__ __launch_bounds__(1024)
void gather_q(const float* __restrict__ cb, const int* __restrict__ idx,
              float* __restrict__ q)
{
    __shared__ float sm[32][33];
    __shared__ int rows[32];
    const int hw0 = blockIdx.x * 32, c0 = blockIdx.y * 32, b = blockIdx.z;
    const int tx = threadIdx.x, ty = threadIdx.y;
    if (ty == 0) rows[tx] = idx[b * 1024 + hw0 + tx];
    __syncthreads();
    sm[ty][tx] = cb[(size_t)rows[ty] * 256 + c0 + tx];
    __syncthreads();
    q[((size_t)(b * 256 + c0 + ty)) * 1024 + hw0 + tx] = sm[tx][ty];
}

__global__ void idx_to_float(const int* __restrict__ idx, float* __restrict__ out)
{
    int t = blockIdx.x * 256 + threadIdx.x;
    if (t < B * 1024) out[t] = (float)idx[t];
}

// ---------------------------------------------------------------------------
// Launch
// ---------------------------------------------------------------------------
extern "C" void kernel_launch(void* const* d_in, const int* in_sizes, int n_in,
                              void* d_out, int out_size)
{
    const float* x   = (const float*)d_in[0];
    const float* ew1 = (const float*)d_in[1];
    const float* eb1 = (const float*)d_in[2];
    const float* ew2 = (const float*)d_in[3];
    const float* eb2 = (const float*)d_in[4];
    const float* ew3 = (const float*)d_in[5];
    const float* eb3 = (const float*)d_in[6];
    const float* cb  = (const float*)d_in[7];
    const float* dw1 = (const float*)d_in[8];
    const float* db1 = (const float*)d_in[9];
    const float* dw2 = (const float*)d_in[10];
    const float* db2 = (const float*)d_in[11];
    const float* dw3 = (const float*)d_in[12];
    const float* db3 = (const float*)d_in[13];
    float* out = (float*)d_out;

    float *h1, *h2, *tok, *q, *d1, *d2, *pv;
    int *idxp, *pip;
    cudaGetSymbolAddress((void**)&h1,  g_h1);
    cudaGetSymbolAddress((void**)&h2,  g_h2);
    cudaGetSymbolAddress((void**)&tok, g_tok);
    cudaGetSymbolAddress((void**)&q,   g_q);
    cudaGetSymbolAddress((void**)&d1,  g_d1);
    cudaGetSymbolAddress((void**)&d2,  g_d2);
    cudaGetSymbolAddress((void**)&idxp,g_idx);
    cudaGetSymbolAddress((void**)&pv,  g_pv);
    cudaGetSymbolAddress((void**)&pip, g_pi);

    static int smem_set = 0;
    if (!smem_set) {
        cudaFuncSetAttribute(argmax_gemm,
                             cudaFuncAttributeMaxDynamicSharedMemorySize,
                             GEMM_SMEM_BYTES);
        smem_set = 1;
    }

    dim3 b16(16, 16);

    // encoder; conv3 writes tok layout directly (fused transpose)
    conv_k4s2_oc16<<<dim3(4, 8, B * 4),  b16>>>(x,  ew1, eb1, h1,  B,   3,  64, 256, 256, 1, 0);
    conv_k4s2_oc16<<<dim3(2, 4, B * 8),  b16>>>(h1, ew2, eb2, h2,  B,  64, 128, 128, 128, 1, 0);
    conv_k4s2_oc16<<<dim3(1, 2, B * 16), b16>>>(h2, ew3, eb3, tok, B, 128, 256,  64,  64, 0, 1);

    // quantize
    argmax_gemm<<<(B * 1024 / 64) * 2, 256, GEMM_SMEM_BYTES>>>(tok, cb, pv, pip);
    merge_idx<<<(B * 1024 + 255) / 256, 256>>>(pv, pip, idxp);
    gather_q<<<dim3(32, 8, B), dim3(32, 32)>>>(cb, idxp, q);

    // decoder
    deconv_k4s2_oc16<<<dim3(2, 4, B * 8), b16>>>(q,  dw1, db1, d1, B, 256, 128, 32, 32, 1);
    deconv_k4s2_oc16<<<dim3(4, 8, B * 4), b16>>>(d1, dw2, db2, d2, B, 128,  64, 64, 64, 1);
    deconv_k4s2    <<<dim3(8, 16, B),     b16>>>(d2, dw3, db3, out, B, 64,   3, 128, 128, 0);

    const int recon_elems = B * 3 * 256 * 256;
    if (out_size >= recon_elems + B * 1024)
        idx_to_float<<<(B * 1024 + 255) / 256, 256>>>(idxp, out + recon_elems);
}

// round 13
// speedup vs baseline: 1.0761x; 1.0761x over previous
#include <cuda_runtime.h>
#include <cuda_bf16.h>
#include <math.h>

#define B 16
typedef unsigned long long ull;

// ---------------------------------------------------------------------------
// f32x2 packed helpers (Blackwell dual-fp32 pipe)
// ---------------------------------------------------------------------------
__device__ __forceinline__ void ffma2(ull &acc, ull a, ull b) {
    asm("fma.rn.f32x2 %0, %1, %2, %0;" : "+l"(acc) : "l"(a), "l"(b));
}
__device__ __forceinline__ ull pack2(float a, float b) {
    ull r; asm("mov.b64 %0, {%1, %2};" : "=l"(r) : "f"(a), "f"(b)); return r;
}
__device__ __forceinline__ float2 unpack2(ull v) {
    float2 r; asm("mov.b64 {%0, %1}, %2;" : "=f"(r.x), "=f"(r.y) : "l"(v)); return r;
}

// ---------------------------------------------------------------------------
// Scratch (device globals; no allocation allowed)
// ---------------------------------------------------------------------------
__device__ float g_h1[B*64*128*128];
__device__ float g_h2[B*128*64*64];
__device__ float g_tok[B*1024*256];
__device__ float g_q[B*256*32*32];
__device__ float g_d1[B*128*64*64];
__device__ float g_d2[B*64*128*128];
__device__ int   g_idx[B*1024];
__device__ float g_pv[4*B*1024];
__device__ int   g_pi[4*B*1024];

// ---------------------------------------------------------------------------
// Direct conv k=4 s=2 p=1, 16 oc per block, 2 pixels/thread (verified).
// tok_mode=1: write y[token][channel] (fused transpose for conv3).
// ---------------------------------------------------------------------------
__global__ __launch_bounds__(256, 2)
void conv_k4s2_oc16(const float* __restrict__ x, const float* __restrict__ w,
                    const float* __restrict__ bias, float* __restrict__ y,
                    int N, int Cin, int Cout, int Hin, int Win, int relu,
                    int tok_mode)
{
    const int Hout = Hin >> 1, Wout = Win >> 1;
    const int ng = (Cout + 15) >> 4;
    const int n  = blockIdx.z / ng;
    const int oc0 = (blockIdx.z % ng) << 4;
    const int ox0 = blockIdx.x * 32 + threadIdx.x;
    const int oy  = blockIdx.y * 16 + threadIdx.y;
    const int tid = threadIdx.y * 16 + threadIdx.x;

    __shared__ float wsm[32][16][16];

    int iy[4]; bool oky[4];
    int ixA[4], ixB[4]; bool okA[4], okB[4];
#pragma unroll
    for (int k = 0; k < 4; k++) {
        int t = oy * 2 + k - 1;
        iy[k] = t; oky[k] = (unsigned)t < (unsigned)Hin;
        int sA = ox0 * 2 + k - 1;
        ixA[k] = sA; okA[k] = (unsigned)sA < (unsigned)Win;
        int sB = sA + 32;
        ixB[k] = sB; okB[k] = (unsigned)sB < (unsigned)Win;
    }

    ull acc[2][8];
#pragma unroll
    for (int p = 0; p < 2; p++)
#pragma unroll
        for (int j = 0; j < 8; j++) acc[p][j] = 0ull;

    for (int ic0 = 0; ic0 < Cin; ic0 += 32) {
        const int icc = min(32, Cin - ic0);
        __syncthreads();
        for (int i = tid; i < icc * 256; i += 256) {
            int c = i >> 8, rem = i & 255, t = rem >> 4, o = rem & 15;
            float wv = 0.f;
            if (oc0 + o < Cout)
                wv = w[(((oc0 + o) * Cin + ic0 + c) << 4) + t];
            wsm[c][t][o] = wv;
        }
        __syncthreads();

        const float* xp = x + ((size_t)(n * Cin + ic0) * Hin) * Win;
        for (int c = 0; c < icc; c++) {
            const float* xc = xp + (size_t)c * Hin * Win;
#pragma unroll
            for (int ky = 0; ky < 4; ky++) {
                if (!oky[ky]) continue;
                const float* xr = xc + iy[ky] * Win;
#pragma unroll
                for (int kx = 0; kx < 4; kx++) {
                    float v0 = okA[kx] ? __ldg(&xr[ixA[kx]]) : 0.f;
                    float v1 = okB[kx] ? __ldg(&xr[ixB[kx]]) : 0.f;
                    ull v0d = pack2(v0, v0);
                    ull v1d = pack2(v1, v1);
                    const ulonglong2* wq = (const ulonglong2*)&wsm[c][ky * 4 + kx][0];
                    ulonglong2 wv0 = wq[0];
                    ulonglong2 wv1 = wq[1];
                    ulonglong2 wv2 = wq[2];
                    ulonglong2 wv3 = wq[3];
                    ffma2(acc[0][0], v0d, wv0.x); ffma2(acc[1][0], v1d, wv0.x);
                    ffma2(acc[0][1], v0d, wv0.y); ffma2(acc[1][1], v1d, wv0.y);
                    ffma2(acc[0][2], v0d, wv1.x); ffma2(acc[1][2], v1d, wv1.x);
                    ffma2(acc[0][3], v0d, wv1.y); ffma2(acc[1][3], v1d, wv1.y);
                    ffma2(acc[0][4], v0d, wv2.x); ffma2(acc[1][4], v1d, wv2.x);
                    ffma2(acc[0][5], v0d, wv2.y); ffma2(acc[1][5], v1d, wv2.y);
                    ffma2(acc[0][6], v0d, wv3.x); ffma2(acc[1][6], v1d, wv3.x);
                    ffma2(acc[0][7], v0d, wv3.y); ffma2(acc[1][7], v1d, wv3.y);
                }
            }
        }
    }

#pragma unroll
    for (int p = 0; p < 2; p++) {
        int ox = ox0 + 16 * p;
        if (ox >= Wout) continue;
        if (tok_mode) {
            float* dst = y + ((size_t)((n * Hout + oy) * Wout + ox)) * Cout + oc0;
#pragma unroll
            for (int j = 0; j < 8; j++) {
                float2 r = unpack2(acc[p][j]);
                r.x += bias[oc0 + 2 * j];
                r.y += bias[oc0 + 2 * j + 1];
                if (relu) { r.x = fmaxf(r.x, 0.f); r.y = fmaxf(r.y, 0.f); }
                *(float2*)&dst[2 * j] = r;
            }
        } else {
#pragma unroll
            for (int j = 0; j < 8; j++) {
                float2 r = unpack2(acc[p][j]);
                int oc = oc0 + 2 * j;
                if (oc < Cout) {
                    float v = r.x + bias[oc];
                    if (relu) v = fmaxf(v, 0.f);
                    y[(((size_t)n * Cout + oc) * Hout + oy) * Wout + ox] = v;
                }
                if (oc + 1 < Cout) {
                    float v = r.y + bias[oc + 1];
                    if (relu) v = fmaxf(v, 0.f);
                    y[(((size_t)n * Cout + oc + 1) * Hout + oy) * Wout + ox] = v;
                }
            }
        }
    }
}

// ---------------------------------------------------------------------------
// Transposed conv k=4 s=2 p=1, 16 oc per block (verified).
// ---------------------------------------------------------------------------
__global__ __launch_bounds__(256, 2)
void deconv_k4s2_oc16(const float* __restrict__ x, const float* __restrict__ w,
                      const float* __restrict__ bias, float* __restrict__ y,
                      int N, int Cin, int Cout, int Hin, int Win, int relu)
{
    const int Hout = Hin << 1, Wout = Win << 1;
    const int ng = (Cout + 15) >> 4;
    const int n  = blockIdx.z / ng;
    const int oc0 = (blockIdx.z % ng) << 4;
    const int ox0 = blockIdx.x * 32 + threadIdx.x;
    const int oy  = blockIdx.y * 16 + threadIdx.y;
    const int tid = threadIdx.y * 16 + threadIdx.x;

    const int pr = oy & 1, q = ox0 & 1;
    int rofs[2], tapy[2]; bool vy[2];
    int ixA[2], ixB[2], tapx[2]; bool vA[2], vB[2];
#pragma unroll
    for (int a = 0; a < 2; a++) {
        int ky = pr + 2 * a; int t = oy + ky - 2;
        rofs[a] = (t >> 1) * Win;
        vy[a] = (t >= 0) && ((t >> 1) < Hin);
        tapy[a] = ky;
        int kx = q + 2 * a;
        int sA = ox0 + kx - 2;
        ixA[a] = sA >> 1; vA[a] = (sA >= 0) && ((sA >> 1) < Win);
        int sB = sA + 16;
        ixB[a] = sB >> 1; vB[a] = (sB >= 0) && ((sB >> 1) < Win);
        tapx[a] = kx;
    }

    __shared__ float wsm[32][16][16];

    ull acc[2][8];
#pragma unroll
    for (int pp = 0; pp < 2; pp++)
#pragma unroll
        for (int j = 0; j < 8; j++) acc[pp][j] = 0ull;

    for (int ic0 = 0; ic0 < Cin; ic0 += 32) {
        const int icc = min(32, Cin - ic0);
        __syncthreads();
        for (int i = tid; i < icc * 256; i += 256) {
            int c = i >> 8, rem = i & 255, t = rem >> 4, o = rem & 15;
            float wv = 0.f;
            if (oc0 + o < Cout)
                wv = w[(((oc0 + o) * Cin + ic0 + c) << 4) + t];
            wsm[c][t][o] = wv;
        }
        __syncthreads();

        const float* xp = x + ((size_t)(n * Cin + ic0) * Hin) * Win;
        for (int c = 0; c < icc; c++) {
            const float* xc = xp + (size_t)c * Hin * Win;
#pragma unroll
            for (int a = 0; a < 2; a++) {
                if (!vy[a]) continue;
                const float* xr = xc + rofs[a];
#pragma unroll
                for (int b2 = 0; b2 < 2; b2++) {
                    float v0 = vA[b2] ? __ldg(&xr[ixA[b2]]) : 0.f;
                    float v1 = vB[b2] ? __ldg(&xr[ixB[b2]]) : 0.f;
                    ull v0d = pack2(v0, v0);
                    ull v1d = pack2(v1, v1);
                    const ulonglong2* wq = (const ulonglong2*)&wsm[c][tapy[a] * 4 + tapx[b2]][0];
                    ulonglong2 wv0 = wq[0];
                    ulonglong2 wv1 = wq[1];
                    ulonglong2 wv2 = wq[2];
                    ulonglong2 wv3 = wq[3];
                    ffma2(acc[0][0], v0d, wv0.x); ffma2(acc[1][0], v1d, wv0.x);
                    ffma2(acc[0][1], v0d, wv0.y); ffma2(acc[1][1], v1d, wv0.y);
                    ffma2(acc[0][2], v0d, wv1.x); ffma2(acc[1][2], v1d, wv1.x);
                    ffma2(acc[0][3], v0d, wv1.y); ffma2(acc[1][3], v1d, wv1.y);
                    ffma2(acc[0][4], v0d, wv2.x); ffma2(acc[1][4], v1d, wv2.x);
                    ffma2(acc[0][5], v0d, wv2.y); ffma2(acc[1][5], v1d, wv2.y);
                    ffma2(acc[0][6], v0d, wv3.x); ffma2(acc[1][6], v1d, wv3.x);
                    ffma2(acc[0][7], v0d, wv3.y); ffma2(acc[1][7], v1d, wv3.y);
                }
            }
        }
    }

#pragma unroll
    for (int pp = 0; pp < 2; pp++) {
        int ox = ox0 + 16 * pp;
        if (ox >= Wout) continue;
#pragma unroll
        for (int j = 0; j < 8; j++) {
            float2 r = unpack2(acc[pp][j]);
            int oc = oc0 + 2 * j;
            if (oc < Cout) {
                float v = r.x + bias[oc];
                if (relu) v = fmaxf(v, 0.f);
                y[(((size_t)n * Cout + oc) * Hout + oy) * Wout + ox] = v;
            }
            if (oc + 1 < Cout) {
                float v = r.y + bias[oc + 1];
                if (relu) v = fmaxf(v, 0.f);
                y[(((size_t)n * Cout + oc + 1) * Hout + oy) * Wout + ox] = v;
            }
        }
    }
}

// ---------------------------------------------------------------------------
// 4-oc deconv (deconv3, Cout=3): halves the padded-oc waste of the 8-oc one.
// Per tap: 2 LDG + 2 pack + 1 LDS.128 + 8 FFMA2.
// ---------------------------------------------------------------------------
__global__ __launch_bounds__(256)
void deconv_k4s2_oc4(const float* __restrict__ x, const float* __restrict__ w,
                     const float* __restrict__ bias, float* __restrict__ y,
                     int N, int Cin, int Cout, int Hin, int Win, int relu)
{
    const int Hout = Hin << 1, Wout = Win << 1;
    const int n  = blockIdx.z;           // one 4-oc group (Cout <= 4)
    const int ox0 = blockIdx.x * 32 + threadIdx.x;
    const int oy  = blockIdx.y * 16 + threadIdx.y;
    const int tid = threadIdx.y * 16 + threadIdx.x;

    const int p = oy & 1, q = ox0 & 1;
    int iyv[2], tapy[2]; bool vy[2];
    int ixA[2], ixB[2], tapx[2]; bool vA[2], vB[2];
#pragma unroll
    for (int a = 0; a < 2; a++) {
        int ky = p + 2 * a; int t = oy + ky - 2;
        iyv[a] = t >> 1; vy[a] = (t >= 0) && ((t >> 1) < Hin); tapy[a] = ky;
        int kx = q + 2 * a;
        int sA = ox0 + kx - 2;
        ixA[a] = sA >> 1; vA[a] = (sA >= 0) && ((sA >> 1) < Win);
        int sB = sA + 16;
        ixB[a] = sB >> 1; vB[a] = (sB >= 0) && ((sB >> 1) < Win);
        tapx[a] = kx;
    }

    __shared__ float wsm[64][16][4];

    ull acc[2][2];
#pragma unroll
    for (int pp = 0; pp < 2; pp++)
#pragma unroll
        for (int j = 0; j < 2; j++) acc[pp][j] = 0ull;

    for (int ic0 = 0; ic0 < Cin; ic0 += 64) {
        const int icc = min(64, Cin - ic0);
        __syncthreads();
        for (int i = tid; i < icc * 64; i += 256) {
            int c = i >> 6, rem = i & 63, t = rem >> 2, o = rem & 3;
            float wv = 0.f;
            if (o < Cout)
                wv = w[((o * Cin + ic0 + c) << 4) + t];
            wsm[c][t][o] = wv;
        }
        __syncthreads();

        const float* xp = x + ((size_t)(n * Cin + ic0) * Hin) * Win;
        for (int c = 0; c < icc; c++) {
            const float* xc = xp + (size_t)c * Hin * Win;
#pragma unroll
            for (int a = 0; a < 2; a++) {
                if (!vy[a]) continue;
                const float* xr = xc + iyv[a] * Win;
#pragma unroll
                for (int b2 = 0; b2 < 2; b2++) {
                    float v0 = vA[b2] ? __ldg(&xr[ixA[b2]]) : 0.f;
                    float v1 = vB[b2] ? __ldg(&xr[ixB[b2]]) : 0.f;
                    ull v0d = pack2(v0, v0);
                    ull v1d = pack2(v1, v1);
                    const ulonglong2 wv0 = *(const ulonglong2*)&wsm[c][tapy[a] * 4 + tapx[b2]][0];
                    ffma2(acc[0][0], v0d, wv0.x); ffma2(acc[1][0], v1d, wv0.x);
                    ffma2(acc[0][1], v0d, wv0.y); ffma2(acc[1][1], v1d, wv0.y);
                }
            }
        }
    }

#pragma unroll
    for (int pp = 0; pp < 2; pp++) {
        int ox = ox0 + 16 * pp;
        if (ox >= Wout) continue;
#pragma unroll
        for (int j = 0; j < 2; j++) {
            float2 r = unpack2(acc[pp][j]);
            int oc = 2 * j;
            if (oc < Cout) {
                float v = r.x + bias[oc];
                if (relu) v = fmaxf(v, 0.f);
                y[(((size_t)n * Cout + oc) * Hout + oy) * Wout + ox] = v;
            }
            if (oc + 1 < Cout) {
                float v = r.y + bias[oc + 1];
                if (relu) v = fmaxf(v, 0.f);
                y[(((size_t)n * Cout + oc + 1) * Hout + oy) * Wout + ox] = v;
            }
        }
    }
}

// ---------------------------------------------------------------------------
// Argmax GEMM v6: v5 micro-tile, cb split into 4 QUARTERS (grid 1024 for
// wave balance), single __syncwarp per stage.
// ---------------------------------------------------------------------------
#define AS_STRIDE 260
#define BSW_STRIDE 68
#define GEMM_SMEM_BYTES ((64*AS_STRIDE + 8*2*8*BSW_STRIDE + 64*8 + 64*8) * 4)

__global__ __launch_bounds__(256, 2)
void argmax_gemm(const float* __restrict__ tok, const float* __restrict__ cb,
                 float* __restrict__ pv, int* __restrict__ pi)
{
    extern __shared__ float dyn[];
    float (*As)[AS_STRIDE] = (float (*)[AS_STRIDE])dyn;
    float (*Bsw)[2][8][BSW_STRIDE] = (float (*)[2][8][BSW_STRIDE])(dyn + 64 * AS_STRIDE);
    float (*rv)[8] = (float (*)[8])(dyn + 64 * AS_STRIDE + 8 * 2 * 8 * BSW_STRIDE);
    int   (*ri)[8] = (int   (*)[8])(dyn + 64 * AS_STRIDE + 8 * 2 * 8 * BSW_STRIDE + 64 * 8);

    const int tid  = threadIdx.x;
    const int wid  = tid >> 5;
    const int lane = tid & 31;
    const int t0 = (blockIdx.x >> 2) * 64;
    const int quarter = blockIdx.x & 3;
    const int jq0 = quarter * 2048;

    const int fr  = tid >> 2;
    const int fca = (tid & 3) << 6;

    const int lr   = lane >> 2;
    const int fcsb = (lane & 3) << 4;
    const int growofs = 8 * wid + lr;

    // ---- fill As once ----
    {
        const float4* src = (const float4*)&tok[(size_t)(t0 + fr) * 256 + fca];
#pragma unroll
        for (int u = 0; u < 16; u++)
            *(float4*)&As[fr][fca + 4 * u] = src[u];
    }

    // ---- warp-private prefetch of stage 0 ----
    float4 pre[4];
    {
        const float4* src = (const float4*)&cb[(size_t)(jq0 + growofs) * 256 + fcsb];
#pragma unroll
        for (int u = 0; u < 4; u++) pre[u] = src[u];
#pragma unroll
        for (int u = 0; u < 4; u++)
            *(float4*)&Bsw[wid][0][lr][fcsb + 4 * u] = pre[u];
    }
    __syncthreads();

    float bv[2]; int bi[2];
#pragma unroll
    for (int m = 0; m < 2; m++) { bv[m] = -INFINITY; bi[m] = 0; }

    ull cacc[2][8];

    for (int s = 0; s < 128; s++) {          // 32 chunks x 4 k-slices
        const int buf = s & 1;
        const int k0 = (s & 3) << 6;

        if ((s & 3) == 0) {
#pragma unroll
            for (int m = 0; m < 2; m++)
#pragma unroll
                for (int nn = 0; nn < 8; nn++) cacc[m][nn] = 0ull;
        }

        if (s < 127) {
            const int s1 = s + 1;
            const int jb = jq0 + (s1 >> 2) * 64;
            const int k1 = (s1 & 3) << 6;
            const float4* src = (const float4*)&cb[(size_t)(jb + growofs) * 256 + k1 + fcsb];
#pragma unroll
            for (int u = 0; u < 4; u++) pre[u] = src[u];
        }

#pragma unroll 4
        for (int kq = 0; kq < 16; kq++) {
            const int ka = k0 + 4 * kq;
            const int kb = 4 * kq;
            ulonglong2 a0 = *(const ulonglong2*)&As[lane][ka];
            ulonglong2 a1 = *(const ulonglong2*)&As[lane + 32][ka];
#pragma unroll
            for (int nn = 0; nn < 8; nn++) {
                ulonglong2 b = *(const ulonglong2*)&Bsw[wid][buf][nn][kb];
                ffma2(cacc[0][nn], a0.x, b.x);
                ffma2(cacc[0][nn], a0.y, b.y);
                ffma2(cacc[1][nn], a1.x, b.x);
                ffma2(cacc[1][nn], a1.y, b.y);
            }
        }

        if ((s & 3) == 3) {
            const int jbase = jq0 + (s >> 2) * 64 + 8 * wid;
#pragma unroll
            for (int m = 0; m < 2; m++)
#pragma unroll
                for (int nn = 0; nn < 8; nn++) {
                    float2 sv = unpack2(cacc[m][nn]);
                    float v = sv.x + sv.y;
                    int j = jbase + nn;
                    if (v > bv[m] || (v == bv[m] && j < bi[m])) { bv[m] = v; bi[m] = j; }
                }
        }

        if (s < 127) {
            // single sync: stores hit buf^1 (disjoint from this stage's reads);
            // sync orders them before the next stage's reads.
#pragma unroll
            for (int u = 0; u < 4; u++)
                *(float4*)&Bsw[wid][(s + 1) & 1][lr][fcsb + 4 * u] = pre[u];
            __syncwarp();
        }
    }

    rv[lane][wid]      = bv[0]; ri[lane][wid]      = bi[0];
    rv[lane + 32][wid] = bv[1]; ri[lane + 32][wid] = bi[1];
    __syncthreads();
    if (tid < 64) {
        float best = rv[tid][0]; int bidx = ri[tid][0];
#pragma unroll
        for (int g = 1; g < 8; g++) {
            float v = rv[tid][g]; int j = ri[tid][g];
            if (v > best || (v == best && j < bidx)) { best = v; bidx = j; }
        }
        pv[quarter * (B * 1024) + t0 + tid] = best;
        pi[quarter * (B * 1024) + t0 + tid] = bidx;
    }
}

__global__ void merge_idx(const float* __restrict__ pv, const int* __restrict__ pi,
                          int* __restrict__ idx)
{
    int t = blockIdx.x * 256 + threadIdx.x;
    if (t >= B * 1024) return;
    float best = pv[t]; int bidx = pi[t];
#pragma unroll
    for (int qd = 1; qd < 4; qd++) {
        float v = pv[qd * (B * 1024) + t];
        // quarters ascend in j; strict > keeps lowest index on ties
        if (v > best) { best = v; bidx = pi[qd * (B * 1024) + t]; }
    }
    idx[t] = bidx;
}

__global__ __launch_bounds__(1024)
void gather_q(const float* __restrict__ cb, const int* __restrict__ idx,
              float* __restrict__ q)
{
    __shared__ float sm[32][33];
    __shared__ int rows[32];
    const int hw0 = blockIdx.x * 32, c0 = blockIdx.y * 32, b = blockIdx.z;
    const int tx = threadIdx.x, ty = threadIdx.y;
    if (ty == 0) rows[tx] = idx[b * 1024 + hw0 + tx];
    __syncthreads();
    sm[ty][tx] = cb[(size_t)rows[ty] * 256 + c0 + tx];
    __syncthreads();
    q[((size_t)(b * 256 + c0 + ty)) * 1024 + hw0 + tx] = sm[tx][ty];
}

__global__ void idx_to_float(const int* __restrict__ idx, float* __restrict__ out)
{
    int t = blockIdx.x * 256 + threadIdx.x;
    if (t < B * 1024) out[t] = (float)idx[t];
}

// ---------------------------------------------------------------------------
// Launch
// ---------------------------------------------------------------------------
extern "C" void kernel_launch(void* const* d_in, const int* in_sizes, int n_in,
                              void* d_out, int out_size)
{
    const float* x   = (const float*)d_in[0];
    const float* ew1 = (const float*)d_in[1];
    const float* eb1 = (const float*)d_in[2];
    const float* ew2 = (const float*)d_in[3];
    const float* eb2 = (const float*)d_in[4];
    const float* ew3 = (const float*)d_in[5];
    const float* eb3 = (const float*)d_in[6];
    const float* cb  = (const float*)d_in[7];
    const float* dw1 = (const float*)d_in[8];
    const float* db1 = (const float*)d_in[9];
    const float* dw2 = (const float*)d_in[10];
    const float* db2 = (const float*)d_in[11];
    const float* dw3 = (const float*)d_in[12];
    const float* db3 = (const float*)d_in[13];
    float* out = (float*)d_out;

    float *h1, *h2, *tok, *q, *d1, *d2, *pv;
    int *idxp, *pip;
    cudaGetSymbolAddress((void**)&h1,  g_h1);
    cudaGetSymbolAddress((void**)&h2,  g_h2);
    cudaGetSymbolAddress((void**)&tok, g_tok);
    cudaGetSymbolAddress((void**)&q,   g_q);
    cudaGetSymbolAddress((void**)&d1,  g_d1);
    cudaGetSymbolAddress((void**)&d2,  g_d2);
    cudaGetSymbolAddress((void**)&idxp,g_idx);
    cudaGetSymbolAddress((void**)&pv,  g_pv);
    cudaGetSymbolAddress((void**)&pip, g_pi);

    static int smem_set = 0;
    if (!smem_set) {
        cudaFuncSetAttribute(argmax_gemm,
                             cudaFuncAttributeMaxDynamicSharedMemorySize,
                             GEMM_SMEM_BYTES);
        smem_set = 1;
    }

    dim3 b16(16, 16);

    // encoder; conv3 writes tok layout directly (fused transpose)
    conv_k4s2_oc16<<<dim3(4, 8, B * 4),  b16>>>(x,  ew1, eb1, h1,  B,   3,  64, 256, 256, 1, 0);
    conv_k4s2_oc16<<<dim3(2, 4, B * 8),  b16>>>(h1, ew2, eb2, h2,  B,  64, 128, 128, 128, 1, 0);
    conv_k4s2_oc16<<<dim3(1, 2, B * 16), b16>>>(h2, ew3, eb3, tok, B, 128, 256,  64,  64, 0, 1);

    // quantize: 4 cb quarters per token-group for wave balance
    argmax_gemm<<<(B * 1024 / 64) * 4, 256, GEMM_SMEM_BYTES>>>(tok, cb, pv, pip);
    merge_idx<<<(B * 1024 + 255) / 256, 256>>>(pv, pip, idxp);
    gather_q<<<dim3(32, 8, B), dim3(32, 32)>>>(cb, idxp, q);

    // decoder
    deconv_k4s2_oc16<<<dim3(2, 4, B * 8), b16>>>(q,  dw1, db1, d1, B, 256, 128, 32, 32, 1);
    deconv_k4s2_oc16<<<dim3(4, 8, B * 4), b16>>>(d1, dw2, db2, d2, B, 128,  64, 64, 64, 1);
    deconv_k4s2_oc4 <<<dim3(8, 16, B),    b16>>>(d2, dw3, db3, out, B, 64,   3, 128, 128, 0);

    const int recon_elems = B * 3 * 256 * 256;
    if (out_size >= recon_elems + B * 1024)
        idx_to_float<<<(B * 1024 + 255) / 256, 256>>>(idxp, out + recon_elems);
}

// round 14
// speedup vs baseline: 1.0769x; 1.0008x over previous
#include <cuda_runtime.h>
#include <cuda_bf16.h>
#include <math.h>

#define B 16
typedef unsigned long long ull;

// ---------------------------------------------------------------------------
// f32x2 packed helpers (Blackwell dual-fp32 pipe)
// ---------------------------------------------------------------------------
__device__ __forceinline__ void ffma2(ull &acc, ull a, ull b) {
    asm("fma.rn.f32x2 %0, %1, %2, %0;" : "+l"(acc) : "l"(a), "l"(b));
}
__device__ __forceinline__ ull pack2(float a, float b) {
    ull r; asm("mov.b64 %0, {%1, %2};" : "=l"(r) : "f"(a), "f"(b)); return r;
}
__device__ __forceinline__ float2 unpack2(ull v) {
    float2 r; asm("mov.b64 {%0, %1}, %2;" : "=f"(r.x), "=f"(r.y) : "l"(v)); return r;
}

// ---------------------------------------------------------------------------
// Scratch (device globals; no allocation allowed)
// ---------------------------------------------------------------------------
__device__ float g_h1[B*64*128*128];
__device__ float g_h2[B*128*64*64];
__device__ float g_tok[B*1024*256];
__device__ float g_q[B*256*32*32];
__device__ float g_d1[B*128*64*64];
__device__ float g_d2[B*64*128*128];
__device__ int   g_idx[B*1024];
__device__ float g_pv[4*B*1024];
__device__ int   g_pi[4*B*1024];

// ---------------------------------------------------------------------------
// Direct conv k=4 s=2 p=1, 16 oc per block, 2 pixels/thread (verified).
// tok_mode=1: write y[token][channel] (fused transpose for conv3).
// ---------------------------------------------------------------------------
__global__ __launch_bounds__(256, 2)
void conv_k4s2_oc16(const float* __restrict__ x, const float* __restrict__ w,
                    const float* __restrict__ bias, float* __restrict__ y,
                    int N, int Cin, int Cout, int Hin, int Win, int relu,
                    int tok_mode)
{
    const int Hout = Hin >> 1, Wout = Win >> 1;
    const int ng = (Cout + 15) >> 4;
    const int n  = blockIdx.z / ng;
    const int oc0 = (blockIdx.z % ng) << 4;
    const int ox0 = blockIdx.x * 32 + threadIdx.x;
    const int oy  = blockIdx.y * 16 + threadIdx.y;
    const int tid = threadIdx.y * 16 + threadIdx.x;

    __shared__ float wsm[32][16][16];

    int iy[4]; bool oky[4];
    int ixA[4], ixB[4]; bool okA[4], okB[4];
#pragma unroll
    for (int k = 0; k < 4; k++) {
        int t = oy * 2 + k - 1;
        iy[k] = t; oky[k] = (unsigned)t < (unsigned)Hin;
        int sA = ox0 * 2 + k - 1;
        ixA[k] = sA; okA[k] = (unsigned)sA < (unsigned)Win;
        int sB = sA + 32;
        ixB[k] = sB; okB[k] = (unsigned)sB < (unsigned)Win;
    }

    ull acc[2][8];
#pragma unroll
    for (int p = 0; p < 2; p++)
#pragma unroll
        for (int j = 0; j < 8; j++) acc[p][j] = 0ull;

    for (int ic0 = 0; ic0 < Cin; ic0 += 32) {
        const int icc = min(32, Cin - ic0);
        __syncthreads();
        for (int i = tid; i < icc * 256; i += 256) {
            int c = i >> 8, rem = i & 255, t = rem >> 4, o = rem & 15;
            float wv = 0.f;
            if (oc0 + o < Cout)
                wv = w[(((oc0 + o) * Cin + ic0 + c) << 4) + t];
            wsm[c][t][o] = wv;
        }
        __syncthreads();

        const float* xp = x + ((size_t)(n * Cin + ic0) * Hin) * Win;
        for (int c = 0; c < icc; c++) {
            const float* xc = xp + (size_t)c * Hin * Win;
#pragma unroll
            for (int ky = 0; ky < 4; ky++) {
                if (!oky[ky]) continue;
                const float* xr = xc + iy[ky] * Win;
#pragma unroll
                for (int kx = 0; kx < 4; kx++) {
                    float v0 = okA[kx] ? __ldg(&xr[ixA[kx]]) : 0.f;
                    float v1 = okB[kx] ? __ldg(&xr[ixB[kx]]) : 0.f;
                    ull v0d = pack2(v0, v0);
                    ull v1d = pack2(v1, v1);
                    const ulonglong2* wq = (const ulonglong2*)&wsm[c][ky * 4 + kx][0];
                    ulonglong2 wv0 = wq[0];
                    ulonglong2 wv1 = wq[1];
                    ulonglong2 wv2 = wq[2];
                    ulonglong2 wv3 = wq[3];
                    ffma2(acc[0][0], v0d, wv0.x); ffma2(acc[1][0], v1d, wv0.x);
                    ffma2(acc[0][1], v0d, wv0.y); ffma2(acc[1][1], v1d, wv0.y);
                    ffma2(acc[0][2], v0d, wv1.x); ffma2(acc[1][2], v1d, wv1.x);
                    ffma2(acc[0][3], v0d, wv1.y); ffma2(acc[1][3], v1d, wv1.y);
                    ffma2(acc[0][4], v0d, wv2.x); ffma2(acc[1][4], v1d, wv2.x);
                    ffma2(acc[0][5], v0d, wv2.y); ffma2(acc[1][5], v1d, wv2.y);
                    ffma2(acc[0][6], v0d, wv3.x); ffma2(acc[1][6], v1d, wv3.x);
                    ffma2(acc[0][7], v0d, wv3.y); ffma2(acc[1][7], v1d, wv3.y);
                }
            }
        }
    }

#pragma unroll
    for (int p = 0; p < 2; p++) {
        int ox = ox0 + 16 * p;
        if (ox >= Wout) continue;
        if (tok_mode) {
            float* dst = y + ((size_t)((n * Hout + oy) * Wout + ox)) * Cout + oc0;
#pragma unroll
            for (int j = 0; j < 8; j++) {
                float2 r = unpack2(acc[p][j]);
                r.x += bias[oc0 + 2 * j];
                r.y += bias[oc0 + 2 * j + 1];
                if (relu) { r.x = fmaxf(r.x, 0.f); r.y = fmaxf(r.y, 0.f); }
                *(float2*)&dst[2 * j] = r;
            }
        } else {
#pragma unroll
            for (int j = 0; j < 8; j++) {
                float2 r = unpack2(acc[p][j]);
                int oc = oc0 + 2 * j;
                if (oc < Cout) {
                    float v = r.x + bias[oc];
                    if (relu) v = fmaxf(v, 0.f);
                    y[(((size_t)n * Cout + oc) * Hout + oy) * Wout + ox] = v;
                }
                if (oc + 1 < Cout) {
                    float v = r.y + bias[oc + 1];
                    if (relu) v = fmaxf(v, 0.f);
                    y[(((size_t)n * Cout + oc + 1) * Hout + oy) * Wout + ox] = v;
                }
            }
        }
    }
}

// ---------------------------------------------------------------------------
// Transposed conv k=4 s=2 p=1, 16 oc per block (verified).
// ---------------------------------------------------------------------------
__global__ __launch_bounds__(256, 2)
void deconv_k4s2_oc16(const float* __restrict__ x, const float* __restrict__ w,
                      const float* __restrict__ bias, float* __restrict__ y,
                      int N, int Cin, int Cout, int Hin, int Win, int relu)
{
    const int Hout = Hin << 1, Wout = Win << 1;
    const int ng = (Cout + 15) >> 4;
    const int n  = blockIdx.z / ng;
    const int oc0 = (blockIdx.z % ng) << 4;
    const int ox0 = blockIdx.x * 32 + threadIdx.x;
    const int oy  = blockIdx.y * 16 + threadIdx.y;
    const int tid = threadIdx.y * 16 + threadIdx.x;

    const int pr = oy & 1, q = ox0 & 1;
    int rofs[2], tapy[2]; bool vy[2];
    int ixA[2], ixB[2], tapx[2]; bool vA[2], vB[2];
#pragma unroll
    for (int a = 0; a < 2; a++) {
        int ky = pr + 2 * a; int t = oy + ky - 2;
        rofs[a] = (t >> 1) * Win;
        vy[a] = (t >= 0) && ((t >> 1) < Hin);
        tapy[a] = ky;
        int kx = q + 2 * a;
        int sA = ox0 + kx - 2;
        ixA[a] = sA >> 1; vA[a] = (sA >= 0) && ((sA >> 1) < Win);
        int sB = sA + 16;
        ixB[a] = sB >> 1; vB[a] = (sB >= 0) && ((sB >> 1) < Win);
        tapx[a] = kx;
    }

    __shared__ float wsm[32][16][16];

    ull acc[2][8];
#pragma unroll
    for (int pp = 0; pp < 2; pp++)
#pragma unroll
        for (int j = 0; j < 8; j++) acc[pp][j] = 0ull;

    for (int ic0 = 0; ic0 < Cin; ic0 += 32) {
        const int icc = min(32, Cin - ic0);
        __syncthreads();
        for (int i = tid; i < icc * 256; i += 256) {
            int c = i >> 8, rem = i & 255, t = rem >> 4, o = rem & 15;
            float wv = 0.f;
            if (oc0 + o < Cout)
                wv = w[(((oc0 + o) * Cin + ic0 + c) << 4) + t];
            wsm[c][t][o] = wv;
        }
        __syncthreads();

        const float* xp = x + ((size_t)(n * Cin + ic0) * Hin) * Win;
        for (int c = 0; c < icc; c++) {
            const float* xc = xp + (size_t)c * Hin * Win;
#pragma unroll
            for (int a = 0; a < 2; a++) {
                if (!vy[a]) continue;
                const float* xr = xc + rofs[a];
#pragma unroll
                for (int b2 = 0; b2 < 2; b2++) {
                    float v0 = vA[b2] ? __ldg(&xr[ixA[b2]]) : 0.f;
                    float v1 = vB[b2] ? __ldg(&xr[ixB[b2]]) : 0.f;
                    ull v0d = pack2(v0, v0);
                    ull v1d = pack2(v1, v1);
                    const ulonglong2* wq = (const ulonglong2*)&wsm[c][tapy[a] * 4 + tapx[b2]][0];
                    ulonglong2 wv0 = wq[0];
                    ulonglong2 wv1 = wq[1];
                    ulonglong2 wv2 = wq[2];
                    ulonglong2 wv3 = wq[3];
                    ffma2(acc[0][0], v0d, wv0.x); ffma2(acc[1][0], v1d, wv0.x);
                    ffma2(acc[0][1], v0d, wv0.y); ffma2(acc[1][1], v1d, wv0.y);
                    ffma2(acc[0][2], v0d, wv1.x); ffma2(acc[1][2], v1d, wv1.x);
                    ffma2(acc[0][3], v0d, wv1.y); ffma2(acc[1][3], v1d, wv1.y);
                    ffma2(acc[0][4], v0d, wv2.x); ffma2(acc[1][4], v1d, wv2.x);
                    ffma2(acc[0][5], v0d, wv2.y); ffma2(acc[1][5], v1d, wv2.y);
                    ffma2(acc[0][6], v0d, wv3.x); ffma2(acc[1][6], v1d, wv3.x);
                    ffma2(acc[0][7], v0d, wv3.y); ffma2(acc[1][7], v1d, wv3.y);
                }
            }
        }
    }

#pragma unroll
    for (int pp = 0; pp < 2; pp++) {
        int ox = ox0 + 16 * pp;
        if (ox >= Wout) continue;
#pragma unroll
        for (int j = 0; j < 8; j++) {
            float2 r = unpack2(acc[pp][j]);
            int oc = oc0 + 2 * j;
            if (oc < Cout) {
                float v = r.x + bias[oc];
                if (relu) v = fmaxf(v, 0.f);
                y[(((size_t)n * Cout + oc) * Hout + oy) * Wout + ox] = v;
            }
            if (oc + 1 < Cout) {
                float v = r.y + bias[oc + 1];
                if (relu) v = fmaxf(v, 0.f);
                y[(((size_t)n * Cout + oc + 1) * Hout + oy) * Wout + ox] = v;
            }
        }
    }
}

// ---------------------------------------------------------------------------
// 4-oc deconv (deconv3, Cout=3): halves the padded-oc waste of the 8-oc one.
// Per tap: 2 LDG + 2 pack + 1 LDS.128 + 8 FFMA2.
// ---------------------------------------------------------------------------
__global__ __launch_bounds__(256)
void deconv_k4s2_oc4(const float* __restrict__ x, const float* __restrict__ w,
                     const float* __restrict__ bias, float* __restrict__ y,
                     int N, int Cin, int Cout, int Hin, int Win, int relu)
{
    const int Hout = Hin << 1, Wout = Win << 1;
    const int n  = blockIdx.z;           // one 4-oc group (Cout <= 4)
    const int ox0 = blockIdx.x * 32 + threadIdx.x;
    const int oy  = blockIdx.y * 16 + threadIdx.y;
    const int tid = threadIdx.y * 16 + threadIdx.x;

    const int p = oy & 1, q = ox0 & 1;
    int iyv[2], tapy[2]; bool vy[2];
    int ixA[2], ixB[2], tapx[2]; bool vA[2], vB[2];
#pragma unroll
    for (int a = 0; a < 2; a++) {
        int ky = p + 2 * a; int t = oy + ky - 2;
        iyv[a] = t >> 1; vy[a] = (t >= 0) && ((t >> 1) < Hin); tapy[a] = ky;
        int kx = q + 2 * a;
        int sA = ox0 + kx - 2;
        ixA[a] = sA >> 1; vA[a] = (sA >= 0) && ((sA >> 1) < Win);
        int sB = sA + 16;
        ixB[a] = sB >> 1; vB[a] = (sB >= 0) && ((sB >> 1) < Win);
        tapx[a] = kx;
    }

    __shared__ float wsm[64][16][4];

    ull acc[2][2];
#pragma unroll
    for (int pp = 0; pp < 2; pp++)
#pragma unroll
        for (int j = 0; j < 2; j++) acc[pp][j] = 0ull;

    for (int ic0 = 0; ic0 < Cin; ic0 += 64) {
        const int icc = min(64, Cin - ic0);
        __syncthreads();
        for (int i = tid; i < icc * 64; i += 256) {
            int c = i >> 6, rem = i & 63, t = rem >> 2, o = rem & 3;
            float wv = 0.f;
            if (o < Cout)
                wv = w[((o * Cin + ic0 + c) << 4) + t];
            wsm[c][t][o] = wv;
        }
        __syncthreads();

        const float* xp = x + ((size_t)(n * Cin + ic0) * Hin) * Win;
        for (int c = 0; c < icc; c++) {
            const float* xc = xp + (size_t)c * Hin * Win;
#pragma unroll
            for (int a = 0; a < 2; a++) {
                if (!vy[a]) continue;
                const float* xr = xc + iyv[a] * Win;
#pragma unroll
                for (int b2 = 0; b2 < 2; b2++) {
                    float v0 = vA[b2] ? __ldg(&xr[ixA[b2]]) : 0.f;
                    float v1 = vB[b2] ? __ldg(&xr[ixB[b2]]) : 0.f;
                    ull v0d = pack2(v0, v0);
                    ull v1d = pack2(v1, v1);
                    const ulonglong2 wv0 = *(const ulonglong2*)&wsm[c][tapy[a] * 4 + tapx[b2]][0];
                    ffma2(acc[0][0], v0d, wv0.x); ffma2(acc[1][0], v1d, wv0.x);
                    ffma2(acc[0][1], v0d, wv0.y); ffma2(acc[1][1], v1d, wv0.y);
                }
            }
        }
    }

#pragma unroll
    for (int pp = 0; pp < 2; pp++) {
        int ox = ox0 + 16 * pp;
        if (ox >= Wout) continue;
#pragma unroll
        for (int j = 0; j < 2; j++) {
            float2 r = unpack2(acc[pp][j]);
            int oc = 2 * j;
            if (oc < Cout) {
                float v = r.x + bias[oc];
                if (relu) v = fmaxf(v, 0.f);
                y[(((size_t)n * Cout + oc) * Hout + oy) * Wout + ox] = v;
            }
            if (oc + 1 < Cout) {
                float v = r.y + bias[oc + 1];
                if (relu) v = fmaxf(v, 0.f);
                y[(((size_t)n * Cout + oc + 1) * Hout + oy) * Wout + ox] = v;
            }
        }
    }
}

// ---------------------------------------------------------------------------
// Argmax GEMM v6: v5 micro-tile, cb split into 4 QUARTERS (grid 1024 for
// wave balance), single __syncwarp per stage.
// ---------------------------------------------------------------------------
#define AS_STRIDE 260
#define BSW_STRIDE 68
#define GEMM_SMEM_BYTES ((64*AS_STRIDE + 8*2*8*BSW_STRIDE + 64*8 + 64*8) * 4)

__global__ __launch_bounds__(256, 2)
void argmax_gemm(const float* __restrict__ tok, const float* __restrict__ cb,
                 float* __restrict__ pv, int* __restrict__ pi)
{
    extern __shared__ float dyn[];
    float (*As)[AS_STRIDE] = (float (*)[AS_STRIDE])dyn;
    float (*Bsw)[2][8][BSW_STRIDE] = (float (*)[2][8][BSW_STRIDE])(dyn + 64 * AS_STRIDE);
    float (*rv)[8] = (float (*)[8])(dyn + 64 * AS_STRIDE + 8 * 2 * 8 * BSW_STRIDE);
    int   (*ri)[8] = (int   (*)[8])(dyn + 64 * AS_STRIDE + 8 * 2 * 8 * BSW_STRIDE + 64 * 8);

    const int tid  = threadIdx.x;
    const int wid  = tid >> 5;
    const int lane = tid & 31;
    const int t0 = (blockIdx.x >> 2) * 64;
    const int quarter = blockIdx.x & 3;
    const int jq0 = quarter * 2048;

    const int fr  = tid >> 2;
    const int fca = (tid & 3) << 6;

    const int lr   = lane >> 2;
    const int fcsb = (lane & 3) << 4;
    const int growofs = 8 * wid + lr;

    // ---- fill As once ----
    {
        const float4* src = (const float4*)&tok[(size_t)(t0 + fr) * 256 + fca];
#pragma unroll
        for (int u = 0; u < 16; u++)
            *(float4*)&As[fr][fca + 4 * u] = src[u];
    }

    // ---- warp-private prefetch of stage 0 ----
    float4 pre[4];
    {
        const float4* src = (const float4*)&cb[(size_t)(jq0 + growofs) * 256 + fcsb];
#pragma unroll
        for (int u = 0; u < 4; u++) pre[u] = src[u];
#pragma unroll
        for (int u = 0; u < 4; u++)
            *(float4*)&Bsw[wid][0][lr][fcsb + 4 * u] = pre[u];
    }
    __syncthreads();

    float bv[2]; int bi[2];
#pragma unroll
    for (int m = 0; m < 2; m++) { bv[m] = -INFINITY; bi[m] = 0; }

    ull cacc[2][8];

    for (int s = 0; s < 128; s++) {          // 32 chunks x 4 k-slices
        const int buf = s & 1;
        const int k0 = (s & 3) << 6;

        if ((s & 3) == 0) {
#pragma unroll
            for (int m = 0; m < 2; m++)
#pragma unroll
                for (int nn = 0; nn < 8; nn++) cacc[m][nn] = 0ull;
        }

        if (s < 127) {
            const int s1 = s + 1;
            const int jb = jq0 + (s1 >> 2) * 64;
            const int k1 = (s1 & 3) << 6;
            const float4* src = (const float4*)&cb[(size_t)(jb + growofs) * 256 + k1 + fcsb];
#pragma unroll
            for (int u = 0; u < 4; u++) pre[u] = src[u];
        }

#pragma unroll 4
        for (int kq = 0; kq < 16; kq++) {
            const int ka = k0 + 4 * kq;
            const int kb = 4 * kq;
            ulonglong2 a0 = *(const ulonglong2*)&As[lane][ka];
            ulonglong2 a1 = *(const ulonglong2*)&As[lane + 32][ka];
#pragma unroll
            for (int nn = 0; nn < 8; nn++) {
                ulonglong2 b = *(const ulonglong2*)&Bsw[wid][buf][nn][kb];
                ffma2(cacc[0][nn], a0.x, b.x);
                ffma2(cacc[0][nn], a0.y, b.y);
                ffma2(cacc[1][nn], a1.x, b.x);
                ffma2(cacc[1][nn], a1.y, b.y);
            }
        }

        if ((s & 3) == 3) {
            const int jbase = jq0 + (s >> 2) * 64 + 8 * wid;
#pragma unroll
            for (int m = 0; m < 2; m++)
#pragma unroll
                for (int nn = 0; nn < 8; nn++) {
                    float2 sv = unpack2(cacc[m][nn]);
                    float v = sv.x + sv.y;
                    int j = jbase + nn;
                    if (v > bv[m] || (v == bv[m] && j < bi[m])) { bv[m] = v; bi[m] = j; }
                }
        }

        if (s < 127) {
            // single sync: stores hit buf^1 (disjoint from this stage's reads);
            // sync orders them before the next stage's reads.
#pragma unroll
            for (int u = 0; u < 4; u++)
                *(float4*)&Bsw[wid][(s + 1) & 1][lr][fcsb + 4 * u] = pre[u];
            __syncwarp();
        }
    }

    rv[lane][wid]      = bv[0]; ri[lane][wid]      = bi[0];
    rv[lane + 32][wid] = bv[1]; ri[lane + 32][wid] = bi[1];
    __syncthreads();
    if (tid < 64) {
        float best = rv[tid][0]; int bidx = ri[tid][0];
#pragma unroll
        for (int g = 1; g < 8; g++) {
            float v = rv[tid][g]; int j = ri[tid][g];
            if (v > best || (v == best && j < bidx)) { best = v; bidx = j; }
        }
        pv[quarter * (B * 1024) + t0 + tid] = best;
        pi[quarter * (B * 1024) + t0 + tid] = bidx;
    }
}

__global__ void merge_idx(const float* __restrict__ pv, const int* __restrict__ pi,
                          int* __restrict__ idx)
{
    int t = blockIdx.x * 256 + threadIdx.x;
    if (t >= B * 1024) return;
    float best = pv[t]; int bidx = pi[t];
#pragma unroll
    for (int qd = 1; qd < 4; qd++) {
        float v = pv[qd * (B * 1024) + t];
        // quarters ascend in j; strict > keeps lowest index on ties
        if (v > best) { best = v; bidx = pi[qd * (B * 1024) + t]; }
    }
    idx[t] = bidx;
}

__global__ __launch_bounds__(1024)
void gather_q(const float* __restrict__ cb, const int* __restrict__ idx,
              float* __restrict__ q)
{
    __shared__ float sm[32][33];
    __shared__ int rows[32];
    const int hw0 = blockIdx.x * 32, c0 = blockIdx.y * 32, b = blockIdx.z;
    const int tx = threadIdx.x, ty = threadIdx.y;
    if (ty == 0) rows[tx] = idx[b * 1024 + hw0 + tx];
    __syncthreads();
    sm[ty][tx] = cb[(size_t)rows[ty] * 256 + c0 + tx];
    __syncthreads();
    q[((size_t)(b * 256 + c0 + ty)) * 1024 + hw0 + tx] = sm[tx][ty];
}

__global__ void idx_to_float(const int* __restrict__ idx, float* __restrict__ out)
{
    int t = blockIdx.x * 256 + threadIdx.x;
    if (t < B * 1024) out[t] = (float)idx[t];
}

// ---------------------------------------------------------------------------
// Launch
// ---------------------------------------------------------------------------
extern "C" void kernel_launch(void* const* d_in, const int* in_sizes, int n_in,
                              void* d_out, int out_size)
{
    const float* x   = (const float*)d_in[0];
    const float* ew1 = (const float*)d_in[1];
    const float* eb1 = (const float*)d_in[2];
    const float* ew2 = (const float*)d_in[3];
    const float* eb2 = (const float*)d_in[4];
    const float* ew3 = (const float*)d_in[5];
    const float* eb3 = (const float*)d_in[6];
    const float* cb  = (const float*)d_in[7];
    const float* dw1 = (const float*)d_in[8];
    const float* db1 = (const float*)d_in[9];
    const float* dw2 = (const float*)d_in[10];
    const float* db2 = (const float*)d_in[11];
    const float* dw3 = (const float*)d_in[12];
    const float* db3 = (const float*)d_in[13];
    float* out = (float*)d_out;

    float *h1, *h2, *tok, *q, *d1, *d2, *pv;
    int *idxp, *pip;
    cudaGetSymbolAddress((void**)&h1,  g_h1);
    cudaGetSymbolAddress((void**)&h2,  g_h2);
    cudaGetSymbolAddress((void**)&tok, g_tok);
    cudaGetSymbolAddress((void**)&q,   g_q);
    cudaGetSymbolAddress((void**)&d1,  g_d1);
    cudaGetSymbolAddress((void**)&d2,  g_d2);
    cudaGetSymbolAddress((void**)&idxp,g_idx);
    cudaGetSymbolAddress((void**)&pv,  g_pv);
    cudaGetSymbolAddress((void**)&pip, g_pi);

    static int smem_set = 0;
    if (!smem_set) {
        cudaFuncSetAttribute(argmax_gemm,
                             cudaFuncAttributeMaxDynamicSharedMemorySize,
                             GEMM_SMEM_BYTES);
        smem_set = 1;
    }

    dim3 b16(16, 16);

    // encoder; conv3 writes tok layout directly (fused transpose)
    conv_k4s2_oc16<<<dim3(4, 8, B * 4),  b16>>>(x,  ew1, eb1, h1,  B,   3,  64, 256, 256, 1, 0);
    conv_k4s2_oc16<<<dim3(2, 4, B * 8),  b16>>>(h1, ew2, eb2, h2,  B,  64, 128, 128, 128, 1, 0);
    conv_k4s2_oc16<<<dim3(1, 2, B * 16), b16>>>(h2, ew3, eb3, tok, B, 128, 256,  64,  64, 0, 1);

    // quantize: 4 cb quarters per token-group for wave balance
    argmax_gemm<<<(B * 1024 / 64) * 4, 256, GEMM_SMEM_BYTES>>>(tok, cb, pv, pip);
    merge_idx<<<(B * 1024 + 255) / 256, 256>>>(pv, pip, idxp);
    gather_q<<<dim3(32, 8, B), dim3(32, 32)>>>(cb, idxp, q);

    // decoder
    deconv_k4s2_oc16<<<dim3(2, 4, B * 8), b16>>>(q,  dw1, db1, d1, B, 256, 128, 32, 32, 1);
    deconv_k4s2_oc16<<<dim3(4, 8, B * 4), b16>>>(d1, dw2, db2, d2, B, 128,  64, 64, 64, 1);
    deconv_k4s2_oc4 <<<dim3(8, 16, B),    b16>>>(d2, dw3, db3, out, B, 64,   3, 128, 128, 0);

    const int recon_elems = B * 3 * 256 * 256;
    if (out_size >= recon_elems + B * 1024)
        idx_to_float<<<(B * 1024 + 255) / 256, 256>>>(idxp, out + recon_elems);
}

// round 15
// speedup vs baseline: 1.1239x; 1.0436x over previous
#include <cuda_runtime.h>
#include <cuda_bf16.h>
#include <math.h>

#define B 16
typedef unsigned long long ull;

// ---------------------------------------------------------------------------
// f32x2 packed helpers (Blackwell dual-fp32 pipe)
// ---------------------------------------------------------------------------
__device__ __forceinline__ void ffma2(ull &acc, ull a, ull b) {
    asm("fma.rn.f32x2 %0, %1, %2, %0;" : "+l"(acc) : "l"(a), "l"(b));
}
__device__ __forceinline__ ull pack2(float a, float b) {
    ull r; asm("mov.b64 %0, {%1, %2};" : "=l"(r) : "f"(a), "f"(b)); return r;
}
__device__ __forceinline__ float2 unpack2(ull v) {
    float2 r; asm("mov.b64 {%0, %1}, %2;" : "=f"(r.x), "=f"(r.y) : "l"(v)); return r;
}

// ---------------------------------------------------------------------------
// Scratch (device globals; no allocation allowed)
// ---------------------------------------------------------------------------
__device__ float g_h1[B*64*128*128];
__device__ float g_h2[B*128*64*64];
__device__ float g_tok[B*1024*256];
__device__ float g_q[B*256*32*32];
__device__ float g_d1[B*128*64*64];
__device__ float g_d2[B*64*128*128];
__device__ int   g_idx[B*1024];
__device__ float g_pv[4*B*1024];
__device__ int   g_pi[4*B*1024];

// ---------------------------------------------------------------------------
// Direct conv k=4 s=2 p=1, 16 oc per block, 2 pixels/thread.
// R15: min-blocks 3 (24 warps/SM) for latency hiding.
// tok_mode=1: write y[token][channel] (fused transpose for conv3).
// ---------------------------------------------------------------------------
__global__ __launch_bounds__(256, 3)
void conv_k4s2_oc16(const float* __restrict__ x, const float* __restrict__ w,
                    const float* __restrict__ bias, float* __restrict__ y,
                    int N, int Cin, int Cout, int Hin, int Win, int relu,
                    int tok_mode)
{
    const int Hout = Hin >> 1, Wout = Win >> 1;
    const int ng = (Cout + 15) >> 4;
    const int n  = blockIdx.z / ng;
    const int oc0 = (blockIdx.z % ng) << 4;
    const int ox0 = blockIdx.x * 32 + threadIdx.x;
    const int oy  = blockIdx.y * 16 + threadIdx.y;
    const int tid = threadIdx.y * 16 + threadIdx.x;

    __shared__ float wsm[32][16][16];

    int iy[4]; bool oky[4];
    int ixA[4], ixB[4]; bool okA[4], okB[4];
#pragma unroll
    for (int k = 0; k < 4; k++) {
        int t = oy * 2 + k - 1;
        iy[k] = t; oky[k] = (unsigned)t < (unsigned)Hin;
        int sA = ox0 * 2 + k - 1;
        ixA[k] = sA; okA[k] = (unsigned)sA < (unsigned)Win;
        int sB = sA + 32;
        ixB[k] = sB; okB[k] = (unsigned)sB < (unsigned)Win;
    }

    ull acc[2][8];
#pragma unroll
    for (int p = 0; p < 2; p++)
#pragma unroll
        for (int j = 0; j < 8; j++) acc[p][j] = 0ull;

    for (int ic0 = 0; ic0 < Cin; ic0 += 32) {
        const int icc = min(32, Cin - ic0);
        __syncthreads();
        for (int i = tid; i < icc * 256; i += 256) {
            int c = i >> 8, rem = i & 255, t = rem >> 4, o = rem & 15;
            float wv = 0.f;
            if (oc0 + o < Cout)
                wv = w[(((oc0 + o) * Cin + ic0 + c) << 4) + t];
            wsm[c][t][o] = wv;
        }
        __syncthreads();

        const float* xp = x + ((size_t)(n * Cin + ic0) * Hin) * Win;
        for (int c = 0; c < icc; c++) {
            const float* xc = xp + (size_t)c * Hin * Win;
#pragma unroll
            for (int ky = 0; ky < 4; ky++) {
                if (!oky[ky]) continue;
                const float* xr = xc + iy[ky] * Win;
#pragma unroll
                for (int kx = 0; kx < 4; kx++) {
                    float v0 = okA[kx] ? __ldg(&xr[ixA[kx]]) : 0.f;
                    float v1 = okB[kx] ? __ldg(&xr[ixB[kx]]) : 0.f;
                    ull v0d = pack2(v0, v0);
                    ull v1d = pack2(v1, v1);
                    const ulonglong2* wq = (const ulonglong2*)&wsm[c][ky * 4 + kx][0];
                    ulonglong2 wv0 = wq[0];
                    ulonglong2 wv1 = wq[1];
                    ulonglong2 wv2 = wq[2];
                    ulonglong2 wv3 = wq[3];
                    ffma2(acc[0][0], v0d, wv0.x); ffma2(acc[1][0], v1d, wv0.x);
                    ffma2(acc[0][1], v0d, wv0.y); ffma2(acc[1][1], v1d, wv0.y);
                    ffma2(acc[0][2], v0d, wv1.x); ffma2(acc[1][2], v1d, wv1.x);
                    ffma2(acc[0][3], v0d, wv1.y); ffma2(acc[1][3], v1d, wv1.y);
                    ffma2(acc[0][4], v0d, wv2.x); ffma2(acc[1][4], v1d, wv2.x);
                    ffma2(acc[0][5], v0d, wv2.y); ffma2(acc[1][5], v1d, wv2.y);
                    ffma2(acc[0][6], v0d, wv3.x); ffma2(acc[1][6], v1d, wv3.x);
                    ffma2(acc[0][7], v0d, wv3.y); ffma2(acc[1][7], v1d, wv3.y);
                }
            }
        }
    }

#pragma unroll
    for (int p = 0; p < 2; p++) {
        int ox = ox0 + 16 * p;
        if (ox >= Wout) continue;
        if (tok_mode) {
            float* dst = y + ((size_t)((n * Hout + oy) * Wout + ox)) * Cout + oc0;
#pragma unroll
            for (int j = 0; j < 8; j++) {
                float2 r = unpack2(acc[p][j]);
                r.x += bias[oc0 + 2 * j];
                r.y += bias[oc0 + 2 * j + 1];
                if (relu) { r.x = fmaxf(r.x, 0.f); r.y = fmaxf(r.y, 0.f); }
                *(float2*)&dst[2 * j] = r;
            }
        } else {
#pragma unroll
            for (int j = 0; j < 8; j++) {
                float2 r = unpack2(acc[p][j]);
                int oc = oc0 + 2 * j;
                if (oc < Cout) {
                    float v = r.x + bias[oc];
                    if (relu) v = fmaxf(v, 0.f);
                    y[(((size_t)n * Cout + oc) * Hout + oy) * Wout + ox] = v;
                }
                if (oc + 1 < Cout) {
                    float v = r.y + bias[oc + 1];
                    if (relu) v = fmaxf(v, 0.f);
                    y[(((size_t)n * Cout + oc + 1) * Hout + oy) * Wout + ox] = v;
                }
            }
        }
    }
}

// ---------------------------------------------------------------------------
// Transposed conv k=4 s=2 p=1, 16 oc per block.  R15: min-blocks 3.
// ---------------------------------------------------------------------------
__global__ __launch_bounds__(256, 3)
void deconv_k4s2_oc16(const float* __restrict__ x, const float* __restrict__ w,
                      const float* __restrict__ bias, float* __restrict__ y,
                      int N, int Cin, int Cout, int Hin, int Win, int relu)
{
    const int Hout = Hin << 1, Wout = Win << 1;
    const int ng = (Cout + 15) >> 4;
    const int n  = blockIdx.z / ng;
    const int oc0 = (blockIdx.z % ng) << 4;
    const int ox0 = blockIdx.x * 32 + threadIdx.x;
    const int oy  = blockIdx.y * 16 + threadIdx.y;
    const int tid = threadIdx.y * 16 + threadIdx.x;

    const int pr = oy & 1, q = ox0 & 1;
    int rofs[2], tapy[2]; bool vy[2];
    int ixA[2], ixB[2], tapx[2]; bool vA[2], vB[2];
#pragma unroll
    for (int a = 0; a < 2; a++) {
        int ky = pr + 2 * a; int t = oy + ky - 2;
        rofs[a] = (t >> 1) * Win;
        vy[a] = (t >= 0) && ((t >> 1) < Hin);
        tapy[a] = ky;
        int kx = q + 2 * a;
        int sA = ox0 + kx - 2;
        ixA[a] = sA >> 1; vA[a] = (sA >= 0) && ((sA >> 1) < Win);
        int sB = sA + 16;
        ixB[a] = sB >> 1; vB[a] = (sB >= 0) && ((sB >> 1) < Win);
        tapx[a] = kx;
    }

    __shared__ float wsm[32][16][16];

    ull acc[2][8];
#pragma unroll
    for (int pp = 0; pp < 2; pp++)
#pragma unroll
        for (int j = 0; j < 8; j++) acc[pp][j] = 0ull;

    for (int ic0 = 0; ic0 < Cin; ic0 += 32) {
        const int icc = min(32, Cin - ic0);
        __syncthreads();
        for (int i = tid; i < icc * 256; i += 256) {
            int c = i >> 8, rem = i & 255, t = rem >> 4, o = rem & 15;
            float wv = 0.f;
            if (oc0 + o < Cout)
                wv = w[(((oc0 + o) * Cin + ic0 + c) << 4) + t];
            wsm[c][t][o] = wv;
        }
        __syncthreads();

        const float* xp = x + ((size_t)(n * Cin + ic0) * Hin) * Win;
        for (int c = 0; c < icc; c++) {
            const float* xc = xp + (size_t)c * Hin * Win;
#pragma unroll
            for (int a = 0; a < 2; a++) {
                if (!vy[a]) continue;
                const float* xr = xc + rofs[a];
#pragma unroll
                for (int b2 = 0; b2 < 2; b2++) {
                    float v0 = vA[b2] ? __ldg(&xr[ixA[b2]]) : 0.f;
                    float v1 = vB[b2] ? __ldg(&xr[ixB[b2]]) : 0.f;
                    ull v0d = pack2(v0, v0);
                    ull v1d = pack2(v1, v1);
                    const ulonglong2* wq = (const ulonglong2*)&wsm[c][tapy[a] * 4 + tapx[b2]][0];
                    ulonglong2 wv0 = wq[0];
                    ulonglong2 wv1 = wq[1];
                    ulonglong2 wv2 = wq[2];
                    ulonglong2 wv3 = wq[3];
                    ffma2(acc[0][0], v0d, wv0.x); ffma2(acc[1][0], v1d, wv0.x);
                    ffma2(acc[0][1], v0d, wv0.y); ffma2(acc[1][1], v1d, wv0.y);
                    ffma2(acc[0][2], v0d, wv1.x); ffma2(acc[1][2], v1d, wv1.x);
                    ffma2(acc[0][3], v0d, wv1.y); ffma2(acc[1][3], v1d, wv1.y);
                    ffma2(acc[0][4], v0d, wv2.x); ffma2(acc[1][4], v1d, wv2.x);
                    ffma2(acc[0][5], v0d, wv2.y); ffma2(acc[1][5], v1d, wv2.y);
                    ffma2(acc[0][6], v0d, wv3.x); ffma2(acc[1][6], v1d, wv3.x);
                    ffma2(acc[0][7], v0d, wv3.y); ffma2(acc[1][7], v1d, wv3.y);
                }
            }
        }
    }

#pragma unroll
    for (int pp = 0; pp < 2; pp++) {
        int ox = ox0 + 16 * pp;
        if (ox >= Wout) continue;
#pragma unroll
        for (int j = 0; j < 8; j++) {
            float2 r = unpack2(acc[pp][j]);
            int oc = oc0 + 2 * j;
            if (oc < Cout) {
                float v = r.x + bias[oc];
                if (relu) v = fmaxf(v, 0.f);
                y[(((size_t)n * Cout + oc) * Hout + oy) * Wout + ox] = v;
            }
            if (oc + 1 < Cout) {
                float v = r.y + bias[oc + 1];
                if (relu) v = fmaxf(v, 0.f);
                y[(((size_t)n * Cout + oc + 1) * Hout + oy) * Wout + ox] = v;
            }
        }
    }
}

// ---------------------------------------------------------------------------
// 4-oc deconv (deconv3, Cout=3).  R15: min-blocks 4.
// ---------------------------------------------------------------------------
__global__ __launch_bounds__(256, 4)
void deconv_k4s2_oc4(const float* __restrict__ x, const float* __restrict__ w,
                     const float* __restrict__ bias, float* __restrict__ y,
                     int N, int Cin, int Cout, int Hin, int Win, int relu)
{
    const int Hout = Hin << 1, Wout = Win << 1;
    const int n  = blockIdx.z;
    const int ox0 = blockIdx.x * 32 + threadIdx.x;
    const int oy  = blockIdx.y * 16 + threadIdx.y;
    const int tid = threadIdx.y * 16 + threadIdx.x;

    const int p = oy & 1, q = ox0 & 1;
    int iyv[2], tapy[2]; bool vy[2];
    int ixA[2], ixB[2], tapx[2]; bool vA[2], vB[2];
#pragma unroll
    for (int a = 0; a < 2; a++) {
        int ky = p + 2 * a; int t = oy + ky - 2;
        iyv[a] = t >> 1; vy[a] = (t >= 0) && ((t >> 1) < Hin); tapy[a] = ky;
        int kx = q + 2 * a;
        int sA = ox0 + kx - 2;
        ixA[a] = sA >> 1; vA[a] = (sA >= 0) && ((sA >> 1) < Win);
        int sB = sA + 16;
        ixB[a] = sB >> 1; vB[a] = (sB >= 0) && ((sB >> 1) < Win);
        tapx[a] = kx;
    }

    __shared__ float wsm[64][16][4];

    ull acc[2][2];
#pragma unroll
    for (int pp = 0; pp < 2; pp++)
#pragma unroll
        for (int j = 0; j < 2; j++) acc[pp][j] = 0ull;

    for (int ic0 = 0; ic0 < Cin; ic0 += 64) {
        const int icc = min(64, Cin - ic0);
        __syncthreads();
        for (int i = tid; i < icc * 64; i += 256) {
            int c = i >> 6, rem = i & 63, t = rem >> 2, o = rem & 3;
            float wv = 0.f;
            if (o < Cout)
                wv = w[((o * Cin + ic0 + c) << 4) + t];
            wsm[c][t][o] = wv;
        }
        __syncthreads();

        const float* xp = x + ((size_t)(n * Cin + ic0) * Hin) * Win;
        for (int c = 0; c < icc; c++) {
            const float* xc = xp + (size_t)c * Hin * Win;
#pragma unroll
            for (int a = 0; a < 2; a++) {
                if (!vy[a]) continue;
                const float* xr = xc + iyv[a] * Win;
#pragma unroll
                for (int b2 = 0; b2 < 2; b2++) {
                    float v0 = vA[b2] ? __ldg(&xr[ixA[b2]]) : 0.f;
                    float v1 = vB[b2] ? __ldg(&xr[ixB[b2]]) : 0.f;
                    ull v0d = pack2(v0, v0);
                    ull v1d = pack2(v1, v1);
                    const ulonglong2 wv0 = *(const ulonglong2*)&wsm[c][tapy[a] * 4 + tapx[b2]][0];
                    ffma2(acc[0][0], v0d, wv0.x); ffma2(acc[1][0], v1d, wv0.x);
                    ffma2(acc[0][1], v0d, wv0.y); ffma2(acc[1][1], v1d, wv0.y);
                }
            }
        }
    }

#pragma unroll
    for (int pp = 0; pp < 2; pp++) {
        int ox = ox0 + 16 * pp;
        if (ox >= Wout) continue;
#pragma unroll
        for (int j = 0; j < 2; j++) {
            float2 r = unpack2(acc[pp][j]);
            int oc = 2 * j;
            if (oc < Cout) {
                float v = r.x + bias[oc];
                if (relu) v = fmaxf(v, 0.f);
                y[(((size_t)n * Cout + oc) * Hout + oy) * Wout + ox] = v;
            }
            if (oc + 1 < Cout) {
                float v = r.y + bias[oc + 1];
                if (relu) v = fmaxf(v, 0.f);
                y[(((size_t)n * Cout + oc + 1) * Hout + oy) * Wout + ox] = v;
            }
        }
    }
}

// ---------------------------------------------------------------------------
// Argmax GEMM v6 (R14, verified): 4 cb quarters, warp-private Bsw,
// single __syncwarp per stage.
// ---------------------------------------------------------------------------
#define AS_STRIDE 260
#define BSW_STRIDE 68
#define GEMM_SMEM_BYTES ((64*AS_STRIDE + 8*2*8*BSW_STRIDE + 64*8 + 64*8) * 4)

__global__ __launch_bounds__(256, 2)
void argmax_gemm(const float* __restrict__ tok, const float* __restrict__ cb,
                 float* __restrict__ pv, int* __restrict__ pi)
{
    extern __shared__ float dyn[];
    float (*As)[AS_STRIDE] = (float (*)[AS_STRIDE])dyn;
    float (*Bsw)[2][8][BSW_STRIDE] = (float (*)[2][8][BSW_STRIDE])(dyn + 64 * AS_STRIDE);
    float (*rv)[8] = (float (*)[8])(dyn + 64 * AS_STRIDE + 8 * 2 * 8 * BSW_STRIDE);
    int   (*ri)[8] = (int   (*)[8])(dyn + 64 * AS_STRIDE + 8 * 2 * 8 * BSW_STRIDE + 64 * 8);

    const int tid  = threadIdx.x;
    const int wid  = tid >> 5;
    const int lane = tid & 31;
    const int t0 = (blockIdx.x >> 2) * 64;
    const int quarter = blockIdx.x & 3;
    const int jq0 = quarter * 2048;

    const int fr  = tid >> 2;
    const int fca = (tid & 3) << 6;

    const int lr   = lane >> 2;
    const int fcsb = (lane & 3) << 4;
    const int growofs = 8 * wid + lr;

    {
        const float4* src = (const float4*)&tok[(size_t)(t0 + fr) * 256 + fca];
#pragma unroll
        for (int u = 0; u < 16; u++)
            *(float4*)&As[fr][fca + 4 * u] = src[u];
    }

    float4 pre[4];
    {
        const float4* src = (const float4*)&cb[(size_t)(jq0 + growofs) * 256 + fcsb];
#pragma unroll
        for (int u = 0; u < 4; u++) pre[u] = src[u];
#pragma unroll
        for (int u = 0; u < 4; u++)
            *(float4*)&Bsw[wid][0][lr][fcsb + 4 * u] = pre[u];
    }
    __syncthreads();

    float bv[2]; int bi[2];
#pragma unroll
    for (int m = 0; m < 2; m++) { bv[m] = -INFINITY; bi[m] = 0; }

    ull cacc[2][8];

    for (int s = 0; s < 128; s++) {
        const int buf = s & 1;
        const int k0 = (s & 3) << 6;

        if ((s & 3) == 0) {
#pragma unroll
            for (int m = 0; m < 2; m++)
#pragma unroll
                for (int nn = 0; nn < 8; nn++) cacc[m][nn] = 0ull;
        }

        if (s < 127) {
            const int s1 = s + 1;
            const int jb = jq0 + (s1 >> 2) * 64;
            const int k1 = (s1 & 3) << 6;
            const float4* src = (const float4*)&cb[(size_t)(jb + growofs) * 256 + k1 + fcsb];
#pragma unroll
            for (int u = 0; u < 4; u++) pre[u] = src[u];
        }

#pragma unroll 4
        for (int kq = 0; kq < 16; kq++) {
            const int ka = k0 + 4 * kq;
            const int kb = 4 * kq;
            ulonglong2 a0 = *(const ulonglong2*)&As[lane][ka];
            ulonglong2 a1 = *(const ulonglong2*)&As[lane + 32][ka];
#pragma unroll
            for (int nn = 0; nn < 8; nn++) {
                ulonglong2 b = *(const ulonglong2*)&Bsw[wid][buf][nn][kb];
                ffma2(cacc[0][nn], a0.x, b.x);
                ffma2(cacc[0][nn], a0.y, b.y);
                ffma2(cacc[1][nn], a1.x, b.x);
                ffma2(cacc[1][nn], a1.y, b.y);
            }
        }

        if ((s & 3) == 3) {
            const int jbase = jq0 + (s >> 2) * 64 + 8 * wid;
#pragma unroll
            for (int m = 0; m < 2; m++)
#pragma unroll
                for (int nn = 0; nn < 8; nn++) {
                    float2 sv = unpack2(cacc[m][nn]);
                    float v = sv.x + sv.y;
                    int j = jbase + nn;
                    if (v > bv[m] || (v == bv[m] && j < bi[m])) { bv[m] = v; bi[m] = j; }
                }
        }

        if (s < 127) {
#pragma unroll
            for (int u = 0; u < 4; u++)
                *(float4*)&Bsw[wid][(s + 1) & 1][lr][fcsb + 4 * u] = pre[u];
            __syncwarp();
        }
    }

    rv[lane][wid]      = bv[0]; ri[lane][wid]      = bi[0];
    rv[lane + 32][wid] = bv[1]; ri[lane + 32][wid] = bi[1];
    __syncthreads();
    if (tid < 64) {
        float best = rv[tid][0]; int bidx = ri[tid][0];
#pragma unroll
        for (int g = 1; g < 8; g++) {
            float v = rv[tid][g]; int j = ri[tid][g];
            if (v > best || (v == best && j < bidx)) { best = v; bidx = j; }
        }
        pv[quarter * (B * 1024) + t0 + tid] = best;
        pi[quarter * (B * 1024) + t0 + tid] = bidx;
    }
}

__global__ void merge_idx(const float* __restrict__ pv, const int* __restrict__ pi,
                          int* __restrict__ idx)
{
    int t = blockIdx.x * 256 + threadIdx.x;
    if (t >= B * 1024) return;
    float best = pv[t]; int bidx = pi[t];
#pragma unroll
    for (int qd = 1; qd < 4; qd++) {
        float v = pv[qd * (B * 1024) + t];
        if (v > best) { best = v; bidx = pi[qd * (B * 1024) + t]; }
    }
    idx[t] = bidx;
}

__global__ __launch_bounds__(1024)
void gather_q(const float* __restrict__ cb, const int* __restrict__ idx,
              float* __restrict__ q)
{
    __shared__ float sm[32][33];
    __shared__ int rows[32];
    const int hw0 = blockIdx.x * 32, c0 = blockIdx.y * 32, b = blockIdx.z;
    const int tx = threadIdx.x, ty = threadIdx.y;
    if (ty == 0) rows[tx] = idx[b * 1024 + hw0 + tx];
    __syncthreads();
    sm[ty][tx] = cb[(size_t)rows[ty] * 256 + c0 + tx];
    __syncthreads();
    q[((size_t)(b * 256 + c0 + ty)) * 1024 + hw0 + tx] = sm[tx][ty];
}

__global__ void idx_to_float(const int* __restrict__ idx, float* __restrict__ out)
{
    int t = blockIdx.x * 256 + threadIdx.x;
    if (t < B * 1024) out[t] = (float)idx[t];
}

// ---------------------------------------------------------------------------
// Launch
// ---------------------------------------------------------------------------
extern "C" void kernel_launch(void* const* d_in, const int* in_sizes, int n_in,
                              void* d_out, int out_size)
{
    const float* x   = (const float*)d_in[0];
    const float* ew1 = (const float*)d_in[1];
    const float* eb1 = (const float*)d_in[2];
    const float* ew2 = (const float*)d_in[3];
    const float* eb2 = (const float*)d_in[4];
    const float* ew3 = (const float*)d_in[5];
    const float* eb3 = (const float*)d_in[6];
    const float* cb  = (const float*)d_in[7];
    const float* dw1 = (const float*)d_in[8];
    const float* db1 = (const float*)d_in[9];
    const float* dw2 = (const float*)d_in[10];
    const float* db2 = (const float*)d_in[11];
    const float* dw3 = (const float*)d_in[12];
    const float* db3 = (const float*)d_in[13];
    float* out = (float*)d_out;

    float *h1, *h2, *tok, *q, *d1, *d2, *pv;
    int *idxp, *pip;
    cudaGetSymbolAddress((void**)&h1,  g_h1);
    cudaGetSymbolAddress((void**)&h2,  g_h2);
    cudaGetSymbolAddress((void**)&tok, g_tok);
    cudaGetSymbolAddress((void**)&q,   g_q);
    cudaGetSymbolAddress((void**)&d1,  g_d1);
    cudaGetSymbolAddress((void**)&d2,  g_d2);
    cudaGetSymbolAddress((void**)&idxp,g_idx);
    cudaGetSymbolAddress((void**)&pv,  g_pv);
    cudaGetSymbolAddress((void**)&pip, g_pi);

    static int smem_set = 0;
    if (!smem_set) {
        cudaFuncSetAttribute(argmax_gemm,
                             cudaFuncAttributeMaxDynamicSharedMemorySize,
                             GEMM_SMEM_BYTES);
        smem_set = 1;
    }

    dim3 b16(16, 16);

    // encoder; conv3 writes tok layout directly (fused transpose)
    conv_k4s2_oc16<<<dim3(4, 8, B * 4),  b16>>>(x,  ew1, eb1, h1,  B,   3,  64, 256, 256, 1, 0);
    conv_k4s2_oc16<<<dim3(2, 4, B * 8),  b16>>>(h1, ew2, eb2, h2,  B,  64, 128, 128, 128, 1, 0);
    conv_k4s2_oc16<<<dim3(1, 2, B * 16), b16>>>(h2, ew3, eb3, tok, B, 128, 256,  64,  64, 0, 1);

    // quantize: 4 cb quarters per token-group for wave balance
    argmax_gemm<<<(B * 1024 / 64) * 4, 256, GEMM_SMEM_BYTES>>>(tok, cb, pv, pip);
    merge_idx<<<(B * 1024 + 255) / 256, 256>>>(pv, pip, idxp);
    gather_q<<<dim3(32, 8, B), dim3(32, 32)>>>(cb, idxp, q);

    // decoder
    deconv_k4s2_oc16<<<dim3(2, 4, B * 8), b16>>>(q,  dw1, db1, d1, B, 256, 128, 32, 32, 1);
    deconv_k4s2_oc16<<<dim3(4, 8, B * 4), b16>>>(d1, dw2, db2, d2, B, 128,  64, 64, 64, 1);
    deconv_k4s2_oc4 <<<dim3(8, 16, B),    b16>>>(d2, dw3, db3, out, B, 64,   3, 128, 128, 0);

    const int recon_elems = B * 3 * 256 * 256;
    if (out_size >= recon_elems + B * 1024)
        idx_to_float<<<(B * 1024 + 255) / 256, 256>>>(idxp, out + recon_elems);
}

// round 16
// speedup vs baseline: 1.1245x; 1.0005x over previous
#include <cuda_runtime.h>
#include <cuda_bf16.h>
#include <math.h>

#define B 16
typedef unsigned long long ull;

// ---------------------------------------------------------------------------
// f32x2 packed helpers (Blackwell dual-fp32 pipe)
// ---------------------------------------------------------------------------
__device__ __forceinline__ void ffma2(ull &acc, ull a, ull b) {
    asm("fma.rn.f32x2 %0, %1, %2, %0;" : "+l"(acc) : "l"(a), "l"(b));
}
__device__ __forceinline__ ull pack2(float a, float b) {
    ull r; asm("mov.b64 %0, {%1, %2};" : "=l"(r) : "f"(a), "f"(b)); return r;
}
__device__ __forceinline__ float2 unpack2(ull v) {
    float2 r; asm("mov.b64 {%0, %1}, %2;" : "=f"(r.x), "=f"(r.y) : "l"(v)); return r;
}

// ---------------------------------------------------------------------------
// Scratch (device globals; no allocation allowed)
// ---------------------------------------------------------------------------
__device__ float g_h1[B*64*128*128];
__device__ float g_h2[B*128*64*64];
__device__ float g_tok[B*1024*256];
__device__ float g_q[B*256*32*32];
__device__ float g_d1[B*128*64*64];
__device__ float g_d2[B*64*128*128];
__device__ int   g_idx[B*1024];
__device__ float g_pv[4*B*1024];
__device__ int   g_pi[4*B*1024];

// ---------------------------------------------------------------------------
// Direct conv k=4 s=2 p=1, 16 oc per block, 2 pixels/thread.
// R15: min-blocks 3 (24 warps/SM) for latency hiding.
// tok_mode=1: write y[token][channel] (fused transpose for conv3).
// ---------------------------------------------------------------------------
__global__ __launch_bounds__(256, 3)
void conv_k4s2_oc16(const float* __restrict__ x, const float* __restrict__ w,
                    const float* __restrict__ bias, float* __restrict__ y,
                    int N, int Cin, int Cout, int Hin, int Win, int relu,
                    int tok_mode)
{
    const int Hout = Hin >> 1, Wout = Win >> 1;
    const int ng = (Cout + 15) >> 4;
    const int n  = blockIdx.z / ng;
    const int oc0 = (blockIdx.z % ng) << 4;
    const int ox0 = blockIdx.x * 32 + threadIdx.x;
    const int oy  = blockIdx.y * 16 + threadIdx.y;
    const int tid = threadIdx.y * 16 + threadIdx.x;

    __shared__ float wsm[32][16][16];

    int iy[4]; bool oky[4];
    int ixA[4], ixB[4]; bool okA[4], okB[4];
#pragma unroll
    for (int k = 0; k < 4; k++) {
        int t = oy * 2 + k - 1;
        iy[k] = t; oky[k] = (unsigned)t < (unsigned)Hin;
        int sA = ox0 * 2 + k - 1;
        ixA[k] = sA; okA[k] = (unsigned)sA < (unsigned)Win;
        int sB = sA + 32;
        ixB[k] = sB; okB[k] = (unsigned)sB < (unsigned)Win;
    }

    ull acc[2][8];
#pragma unroll
    for (int p = 0; p < 2; p++)
#pragma unroll
        for (int j = 0; j < 8; j++) acc[p][j] = 0ull;

    for (int ic0 = 0; ic0 < Cin; ic0 += 32) {
        const int icc = min(32, Cin - ic0);
        __syncthreads();
        for (int i = tid; i < icc * 256; i += 256) {
            int c = i >> 8, rem = i & 255, t = rem >> 4, o = rem & 15;
            float wv = 0.f;
            if (oc0 + o < Cout)
                wv = w[(((oc0 + o) * Cin + ic0 + c) << 4) + t];
            wsm[c][t][o] = wv;
        }
        __syncthreads();

        const float* xp = x + ((size_t)(n * Cin + ic0) * Hin) * Win;
        for (int c = 0; c < icc; c++) {
            const float* xc = xp + (size_t)c * Hin * Win;
#pragma unroll
            for (int ky = 0; ky < 4; ky++) {
                if (!oky[ky]) continue;
                const float* xr = xc + iy[ky] * Win;
#pragma unroll
                for (int kx = 0; kx < 4; kx++) {
                    float v0 = okA[kx] ? __ldg(&xr[ixA[kx]]) : 0.f;
                    float v1 = okB[kx] ? __ldg(&xr[ixB[kx]]) : 0.f;
                    ull v0d = pack2(v0, v0);
                    ull v1d = pack2(v1, v1);
                    const ulonglong2* wq = (const ulonglong2*)&wsm[c][ky * 4 + kx][0];
                    ulonglong2 wv0 = wq[0];
                    ulonglong2 wv1 = wq[1];
                    ulonglong2 wv2 = wq[2];
                    ulonglong2 wv3 = wq[3];
                    ffma2(acc[0][0], v0d, wv0.x); ffma2(acc[1][0], v1d, wv0.x);
                    ffma2(acc[0][1], v0d, wv0.y); ffma2(acc[1][1], v1d, wv0.y);
                    ffma2(acc[0][2], v0d, wv1.x); ffma2(acc[1][2], v1d, wv1.x);
                    ffma2(acc[0][3], v0d, wv1.y); ffma2(acc[1][3], v1d, wv1.y);
                    ffma2(acc[0][4], v0d, wv2.x); ffma2(acc[1][4], v1d, wv2.x);
                    ffma2(acc[0][5], v0d, wv2.y); ffma2(acc[1][5], v1d, wv2.y);
                    ffma2(acc[0][6], v0d, wv3.x); ffma2(acc[1][6], v1d, wv3.x);
                    ffma2(acc[0][7], v0d, wv3.y); ffma2(acc[1][7], v1d, wv3.y);
                }
            }
        }
    }

#pragma unroll
    for (int p = 0; p < 2; p++) {
        int ox = ox0 + 16 * p;
        if (ox >= Wout) continue;
        if (tok_mode) {
            float* dst = y + ((size_t)((n * Hout + oy) * Wout + ox)) * Cout + oc0;
#pragma unroll
            for (int j = 0; j < 8; j++) {
                float2 r = unpack2(acc[p][j]);
                r.x += bias[oc0 + 2 * j];
                r.y += bias[oc0 + 2 * j + 1];
                if (relu) { r.x = fmaxf(r.x, 0.f); r.y = fmaxf(r.y, 0.f); }
                *(float2*)&dst[2 * j] = r;
            }
        } else {
#pragma unroll
            for (int j = 0; j < 8; j++) {
                float2 r = unpack2(acc[p][j]);
                int oc = oc0 + 2 * j;
                if (oc < Cout) {
                    float v = r.x + bias[oc];
                    if (relu) v = fmaxf(v, 0.f);
                    y[(((size_t)n * Cout + oc) * Hout + oy) * Wout + ox] = v;
                }
                if (oc + 1 < Cout) {
                    float v = r.y + bias[oc + 1];
                    if (relu) v = fmaxf(v, 0.f);
                    y[(((size_t)n * Cout + oc + 1) * Hout + oy) * Wout + ox] = v;
                }
            }
        }
    }
}

// ---------------------------------------------------------------------------
// Transposed conv k=4 s=2 p=1, 16 oc per block.  R15: min-blocks 3.
// ---------------------------------------------------------------------------
__global__ __launch_bounds__(256, 3)
void deconv_k4s2_oc16(const float* __restrict__ x, const float* __restrict__ w,
                      const float* __restrict__ bias, float* __restrict__ y,
                      int N, int Cin, int Cout, int Hin, int Win, int relu)
{
    const int Hout = Hin << 1, Wout = Win << 1;
    const int ng = (Cout + 15) >> 4;
    const int n  = blockIdx.z / ng;
    const int oc0 = (blockIdx.z % ng) << 4;
    const int ox0 = blockIdx.x * 32 + threadIdx.x;
    const int oy  = blockIdx.y * 16 + threadIdx.y;
    const int tid = threadIdx.y * 16 + threadIdx.x;

    const int pr = oy & 1, q = ox0 & 1;
    int rofs[2], tapy[2]; bool vy[2];
    int ixA[2], ixB[2], tapx[2]; bool vA[2], vB[2];
#pragma unroll
    for (int a = 0; a < 2; a++) {
        int ky = pr + 2 * a; int t = oy + ky - 2;
        rofs[a] = (t >> 1) * Win;
        vy[a] = (t >= 0) && ((t >> 1) < Hin);
        tapy[a] = ky;
        int kx = q + 2 * a;
        int sA = ox0 + kx - 2;
        ixA[a] = sA >> 1; vA[a] = (sA >= 0) && ((sA >> 1) < Win);
        int sB = sA + 16;
        ixB[a] = sB >> 1; vB[a] = (sB >= 0) && ((sB >> 1) < Win);
        tapx[a] = kx;
    }

    __shared__ float wsm[32][16][16];

    ull acc[2][8];
#pragma unroll
    for (int pp = 0; pp < 2; pp++)
#pragma unroll
        for (int j = 0; j < 8; j++) acc[pp][j] = 0ull;

    for (int ic0 = 0; ic0 < Cin; ic0 += 32) {
        const int icc = min(32, Cin - ic0);
        __syncthreads();
        for (int i = tid; i < icc * 256; i += 256) {
            int c = i >> 8, rem = i & 255, t = rem >> 4, o = rem & 15;
            float wv = 0.f;
            if (oc0 + o < Cout)
                wv = w[(((oc0 + o) * Cin + ic0 + c) << 4) + t];
            wsm[c][t][o] = wv;
        }
        __syncthreads();

        const float* xp = x + ((size_t)(n * Cin + ic0) * Hin) * Win;
        for (int c = 0; c < icc; c++) {
            const float* xc = xp + (size_t)c * Hin * Win;
#pragma unroll
            for (int a = 0; a < 2; a++) {
                if (!vy[a]) continue;
                const float* xr = xc + rofs[a];
#pragma unroll
                for (int b2 = 0; b2 < 2; b2++) {
                    float v0 = vA[b2] ? __ldg(&xr[ixA[b2]]) : 0.f;
                    float v1 = vB[b2] ? __ldg(&xr[ixB[b2]]) : 0.f;
                    ull v0d = pack2(v0, v0);
                    ull v1d = pack2(v1, v1);
                    const ulonglong2* wq = (const ulonglong2*)&wsm[c][tapy[a] * 4 + tapx[b2]][0];
                    ulonglong2 wv0 = wq[0];
                    ulonglong2 wv1 = wq[1];
                    ulonglong2 wv2 = wq[2];
                    ulonglong2 wv3 = wq[3];
                    ffma2(acc[0][0], v0d, wv0.x); ffma2(acc[1][0], v1d, wv0.x);
                    ffma2(acc[0][1], v0d, wv0.y); ffma2(acc[1][1], v1d, wv0.y);
                    ffma2(acc[0][2], v0d, wv1.x); ffma2(acc[1][2], v1d, wv1.x);
                    ffma2(acc[0][3], v0d, wv1.y); ffma2(acc[1][3], v1d, wv1.y);
                    ffma2(acc[0][4], v0d, wv2.x); ffma2(acc[1][4], v1d, wv2.x);
                    ffma2(acc[0][5], v0d, wv2.y); ffma2(acc[1][5], v1d, wv2.y);
                    ffma2(acc[0][6], v0d, wv3.x); ffma2(acc[1][6], v1d, wv3.x);
                    ffma2(acc[0][7], v0d, wv3.y); ffma2(acc[1][7], v1d, wv3.y);
                }
            }
        }
    }

#pragma unroll
    for (int pp = 0; pp < 2; pp++) {
        int ox = ox0 + 16 * pp;
        if (ox >= Wout) continue;
#pragma unroll
        for (int j = 0; j < 8; j++) {
            float2 r = unpack2(acc[pp][j]);
            int oc = oc0 + 2 * j;
            if (oc < Cout) {
                float v = r.x + bias[oc];
                if (relu) v = fmaxf(v, 0.f);
                y[(((size_t)n * Cout + oc) * Hout + oy) * Wout + ox] = v;
            }
            if (oc + 1 < Cout) {
                float v = r.y + bias[oc + 1];
                if (relu) v = fmaxf(v, 0.f);
                y[(((size_t)n * Cout + oc + 1) * Hout + oy) * Wout + ox] = v;
            }
        }
    }
}

// ---------------------------------------------------------------------------
// 4-oc deconv (deconv3, Cout=3).  R15: min-blocks 4.
// ---------------------------------------------------------------------------
__global__ __launch_bounds__(256, 4)
void deconv_k4s2_oc4(const float* __restrict__ x, const float* __restrict__ w,
                     const float* __restrict__ bias, float* __restrict__ y,
                     int N, int Cin, int Cout, int Hin, int Win, int relu)
{
    const int Hout = Hin << 1, Wout = Win << 1;
    const int n  = blockIdx.z;
    const int ox0 = blockIdx.x * 32 + threadIdx.x;
    const int oy  = blockIdx.y * 16 + threadIdx.y;
    const int tid = threadIdx.y * 16 + threadIdx.x;

    const int p = oy & 1, q = ox0 & 1;
    int iyv[2], tapy[2]; bool vy[2];
    int ixA[2], ixB[2], tapx[2]; bool vA[2], vB[2];
#pragma unroll
    for (int a = 0; a < 2; a++) {
        int ky = p + 2 * a; int t = oy + ky - 2;
        iyv[a] = t >> 1; vy[a] = (t >= 0) && ((t >> 1) < Hin); tapy[a] = ky;
        int kx = q + 2 * a;
        int sA = ox0 + kx - 2;
        ixA[a] = sA >> 1; vA[a] = (sA >= 0) && ((sA >> 1) < Win);
        int sB = sA + 16;
        ixB[a] = sB >> 1; vB[a] = (sB >= 0) && ((sB >> 1) < Win);
        tapx[a] = kx;
    }

    __shared__ float wsm[64][16][4];

    ull acc[2][2];
#pragma unroll
    for (int pp = 0; pp < 2; pp++)
#pragma unroll
        for (int j = 0; j < 2; j++) acc[pp][j] = 0ull;

    for (int ic0 = 0; ic0 < Cin; ic0 += 64) {
        const int icc = min(64, Cin - ic0);
        __syncthreads();
        for (int i = tid; i < icc * 64; i += 256) {
            int c = i >> 6, rem = i & 63, t = rem >> 2, o = rem & 3;
            float wv = 0.f;
            if (o < Cout)
                wv = w[((o * Cin + ic0 + c) << 4) + t];
            wsm[c][t][o] = wv;
        }
        __syncthreads();

        const float* xp = x + ((size_t)(n * Cin + ic0) * Hin) * Win;
        for (int c = 0; c < icc; c++) {
            const float* xc = xp + (size_t)c * Hin * Win;
#pragma unroll
            for (int a = 0; a < 2; a++) {
                if (!vy[a]) continue;
                const float* xr = xc + iyv[a] * Win;
#pragma unroll
                for (int b2 = 0; b2 < 2; b2++) {
                    float v0 = vA[b2] ? __ldg(&xr[ixA[b2]]) : 0.f;
                    float v1 = vB[b2] ? __ldg(&xr[ixB[b2]]) : 0.f;
                    ull v0d = pack2(v0, v0);
                    ull v1d = pack2(v1, v1);
                    const ulonglong2 wv0 = *(const ulonglong2*)&wsm[c][tapy[a] * 4 + tapx[b2]][0];
                    ffma2(acc[0][0], v0d, wv0.x); ffma2(acc[1][0], v1d, wv0.x);
                    ffma2(acc[0][1], v0d, wv0.y); ffma2(acc[1][1], v1d, wv0.y);
                }
            }
        }
    }

#pragma unroll
    for (int pp = 0; pp < 2; pp++) {
        int ox = ox0 + 16 * pp;
        if (ox >= Wout) continue;
#pragma unroll
        for (int j = 0; j < 2; j++) {
            float2 r = unpack2(acc[pp][j]);
            int oc = 2 * j;
            if (oc < Cout) {
                float v = r.x + bias[oc];
                if (relu) v = fmaxf(v, 0.f);
                y[(((size_t)n * Cout + oc) * Hout + oy) * Wout + ox] = v;
            }
            if (oc + 1 < Cout) {
                float v = r.y + bias[oc + 1];
                if (relu) v = fmaxf(v, 0.f);
                y[(((size_t)n * Cout + oc + 1) * Hout + oy) * Wout + ox] = v;
            }
        }
    }
}

// ---------------------------------------------------------------------------
// Argmax GEMM v6 (R14, verified): 4 cb quarters, warp-private Bsw,
// single __syncwarp per stage.
// ---------------------------------------------------------------------------
#define AS_STRIDE 260
#define BSW_STRIDE 68
#define GEMM_SMEM_BYTES ((64*AS_STRIDE + 8*2*8*BSW_STRIDE + 64*8 + 64*8) * 4)

__global__ __launch_bounds__(256, 2)
void argmax_gemm(const float* __restrict__ tok, const float* __restrict__ cb,
                 float* __restrict__ pv, int* __restrict__ pi)
{
    extern __shared__ float dyn[];
    float (*As)[AS_STRIDE] = (float (*)[AS_STRIDE])dyn;
    float (*Bsw)[2][8][BSW_STRIDE] = (float (*)[2][8][BSW_STRIDE])(dyn + 64 * AS_STRIDE);
    float (*rv)[8] = (float (*)[8])(dyn + 64 * AS_STRIDE + 8 * 2 * 8 * BSW_STRIDE);
    int   (*ri)[8] = (int   (*)[8])(dyn + 64 * AS_STRIDE + 8 * 2 * 8 * BSW_STRIDE + 64 * 8);

    const int tid  = threadIdx.x;
    const int wid  = tid >> 5;
    const int lane = tid & 31;
    const int t0 = (blockIdx.x >> 2) * 64;
    const int quarter = blockIdx.x & 3;
    const int jq0 = quarter * 2048;

    const int fr  = tid >> 2;
    const int fca = (tid & 3) << 6;

    const int lr   = lane >> 2;
    const int fcsb = (lane & 3) << 4;
    const int growofs = 8 * wid + lr;

    {
        const float4* src = (const float4*)&tok[(size_t)(t0 + fr) * 256 + fca];
#pragma unroll
        for (int u = 0; u < 16; u++)
            *(float4*)&As[fr][fca + 4 * u] = src[u];
    }

    float4 pre[4];
    {
        const float4* src = (const float4*)&cb[(size_t)(jq0 + growofs) * 256 + fcsb];
#pragma unroll
        for (int u = 0; u < 4; u++) pre[u] = src[u];
#pragma unroll
        for (int u = 0; u < 4; u++)
            *(float4*)&Bsw[wid][0][lr][fcsb + 4 * u] = pre[u];
    }
    __syncthreads();

    float bv[2]; int bi[2];
#pragma unroll
    for (int m = 0; m < 2; m++) { bv[m] = -INFINITY; bi[m] = 0; }

    ull cacc[2][8];

    for (int s = 0; s < 128; s++) {
        const int buf = s & 1;
        const int k0 = (s & 3) << 6;

        if ((s & 3) == 0) {
#pragma unroll
            for (int m = 0; m < 2; m++)
#pragma unroll
                for (int nn = 0; nn < 8; nn++) cacc[m][nn] = 0ull;
        }

        if (s < 127) {
            const int s1 = s + 1;
            const int jb = jq0 + (s1 >> 2) * 64;
            const int k1 = (s1 & 3) << 6;
            const float4* src = (const float4*)&cb[(size_t)(jb + growofs) * 256 + k1 + fcsb];
#pragma unroll
            for (int u = 0; u < 4; u++) pre[u] = src[u];
        }

#pragma unroll 4
        for (int kq = 0; kq < 16; kq++) {
            const int ka = k0 + 4 * kq;
            const int kb = 4 * kq;
            ulonglong2 a0 = *(const ulonglong2*)&As[lane][ka];
            ulonglong2 a1 = *(const ulonglong2*)&As[lane + 32][ka];
#pragma unroll
            for (int nn = 0; nn < 8; nn++) {
                ulonglong2 b = *(const ulonglong2*)&Bsw[wid][buf][nn][kb];
                ffma2(cacc[0][nn], a0.x, b.x);
                ffma2(cacc[0][nn], a0.y, b.y);
                ffma2(cacc[1][nn], a1.x, b.x);
                ffma2(cacc[1][nn], a1.y, b.y);
            }
        }

        if ((s & 3) == 3) {
            const int jbase = jq0 + (s >> 2) * 64 + 8 * wid;
#pragma unroll
            for (int m = 0; m < 2; m++)
#pragma unroll
                for (int nn = 0; nn < 8; nn++) {
                    float2 sv = unpack2(cacc[m][nn]);
                    float v = sv.x + sv.y;
                    int j = jbase + nn;
                    if (v > bv[m] || (v == bv[m] && j < bi[m])) { bv[m] = v; bi[m] = j; }
                }
        }

        if (s < 127) {
#pragma unroll
            for (int u = 0; u < 4; u++)
                *(float4*)&Bsw[wid][(s + 1) & 1][lr][fcsb + 4 * u] = pre[u];
            __syncwarp();
        }
    }

    rv[lane][wid]      = bv[0]; ri[lane][wid]      = bi[0];
    rv[lane + 32][wid] = bv[1]; ri[lane + 32][wid] = bi[1];
    __syncthreads();
    if (tid < 64) {
        float best = rv[tid][0]; int bidx = ri[tid][0];
#pragma unroll
        for (int g = 1; g < 8; g++) {
            float v = rv[tid][g]; int j = ri[tid][g];
            if (v > best || (v == best && j < bidx)) { best = v; bidx = j; }
        }
        pv[quarter * (B * 1024) + t0 + tid] = best;
        pi[quarter * (B * 1024) + t0 + tid] = bidx;
    }
}

__global__ void merge_idx(const float* __restrict__ pv, const int* __restrict__ pi,
                          int* __restrict__ idx)
{
    int t = blockIdx.x * 256 + threadIdx.x;
    if (t >= B * 1024) return;
    float best = pv[t]; int bidx = pi[t];
#pragma unroll
    for (int qd = 1; qd < 4; qd++) {
        float v = pv[qd * (B * 1024) + t];
        if (v > best) { best = v; bidx = pi[qd * (B * 1024) + t]; }
    }
    idx[t] = bidx;
}

__global__ __launch_bounds__(1024)
void gather_q(const float* __restrict__ cb, const int* __restrict__ idx,
              float* __restrict__ q)
{
    __shared__ float sm[32][33];
    __shared__ int rows[32];
    const int hw0 = blockIdx.x * 32, c0 = blockIdx.y * 32, b = blockIdx.z;
    const int tx = threadIdx.x, ty = threadIdx.y;
    if (ty == 0) rows[tx] = idx[b * 1024 + hw0 + tx];
    __syncthreads();
    sm[ty][tx] = cb[(size_t)rows[ty] * 256 + c0 + tx];
    __syncthreads();
    q[((size_t)(b * 256 + c0 + ty)) * 1024 + hw0 + tx] = sm[tx][ty];
}

__global__ void idx_to_float(const int* __restrict__ idx, float* __restrict__ out)
{
    int t = blockIdx.x * 256 + threadIdx.x;
    if (t < B * 1024) out[t] = (float)idx[t];
}

// ---------------------------------------------------------------------------
// Launch
// ---------------------------------------------------------------------------
extern "C" void kernel_launch(void* const* d_in, const int* in_sizes, int n_in,
                              void* d_out, int out_size)
{
    const float* x   = (const float*)d_in[0];
    const float* ew1 = (const float*)d_in[1];
    const float* eb1 = (const float*)d_in[2];
    const float* ew2 = (const float*)d_in[3];
    const float* eb2 = (const float*)d_in[4];
    const float* ew3 = (const float*)d_in[5];
    const float* eb3 = (const float*)d_in[6];
    const float* cb  = (const float*)d_in[7];
    const float* dw1 = (const float*)d_in[8];
    const float* db1 = (const float*)d_in[9];
    const float* dw2 = (const float*)d_in[10];
    const float* db2 = (const float*)d_in[11];
    const float* dw3 = (const float*)d_in[12];
    const float* db3 = (const float*)d_in[13];
    float* out = (float*)d_out;

    float *h1, *h2, *tok, *q, *d1, *d2, *pv;
    int *idxp, *pip;
    cudaGetSymbolAddress((void**)&h1,  g_h1);
    cudaGetSymbolAddress((void**)&h2,  g_h2);
    cudaGetSymbolAddress((void**)&tok, g_tok);
    cudaGetSymbolAddress((void**)&q,   g_q);
    cudaGetSymbolAddress((void**)&d1,  g_d1);
    cudaGetSymbolAddress((void**)&d2,  g_d2);
    cudaGetSymbolAddress((void**)&idxp,g_idx);
    cudaGetSymbolAddress((void**)&pv,  g_pv);
    cudaGetSymbolAddress((void**)&pip, g_pi);

    static int smem_set = 0;
    if (!smem_set) {
        cudaFuncSetAttribute(argmax_gemm,
                             cudaFuncAttributeMaxDynamicSharedMemorySize,
                             GEMM_SMEM_BYTES);
        smem_set = 1;
    }

    dim3 b16(16, 16);

    // encoder; conv3 writes tok layout directly (fused transpose)
    conv_k4s2_oc16<<<dim3(4, 8, B * 4),  b16>>>(x,  ew1, eb1, h1,  B,   3,  64, 256, 256, 1, 0);
    conv_k4s2_oc16<<<dim3(2, 4, B * 8),  b16>>>(h1, ew2, eb2, h2,  B,  64, 128, 128, 128, 1, 0);
    conv_k4s2_oc16<<<dim3(1, 2, B * 16), b16>>>(h2, ew3, eb3, tok, B, 128, 256,  64,  64, 0, 1);

    // quantize: 4 cb quarters per token-group for wave balance
    argmax_gemm<<<(B * 1024 / 64) * 4, 256, GEMM_SMEM_BYTES>>>(tok, cb, pv, pip);
    merge_idx<<<(B * 1024 + 255) / 256, 256>>>(pv, pip, idxp);
    gather_q<<<dim3(32, 8, B), dim3(32, 32)>>>(cb, idxp, q);

    // decoder
    deconv_k4s2_oc16<<<dim3(2, 4, B * 8), b16>>>(q,  dw1, db1, d1, B, 256, 128, 32, 32, 1);
    deconv_k4s2_oc16<<<dim3(4, 8, B * 4), b16>>>(d1, dw2, db2, d2, B, 128,  64, 64, 64, 1);
    deconv_k4s2_oc4 <<<dim3(8, 16, B),    b16>>>(d2, dw3, db3, out, B, 64,   3, 128, 128, 0);

    const int recon_elems = B * 3 * 256 * 256;
    if (out_size >= recon_elems + B * 1024)
        idx_to_float<<<(B * 1024 + 255) / 256, 256>>>(idxp, out + recon_elems);
}